// round 6
// baseline (speedup 1.0000x reference)
#include <cuda_runtime.h>

// ---------------- scratch (static device globals; no allocation) ----------------
__device__ float g_y1[32 * 24 * 32 * 32];   // conv1 raw output (pre-BN)
__device__ float g_y2[32 * 24 * 16 * 16];   // conv2 raw output (pre-BN)
__device__ float g_part1s[24 * 128];        // conv1 per-block channel sums
__device__ float g_part1q[24 * 128];
__device__ float g_part2s[24 * 64];         // conv2: key = n*2+half
__device__ float g_part2q[24 * 64];
__device__ float g_hpart[32 * 8 * 2];       // per-(n,chunk) fc2 partials
__device__ unsigned g_done[32];             // per-n ticket, zero-init, self-reset
__device__ unsigned g_cnt1[16 * 32];        // group counters, padded to 128B lines
__device__ unsigned g_cnt2;                 // root counter
__device__ volatile unsigned g_bar_gen;

#define NBLOCKS 256

__device__ __forceinline__ float warp_sum(float v) {
#pragma unroll
    for (int o = 16; o > 0; o >>= 1) v += __shfl_down_sync(0xffffffffu, v, o);
    return v;
}

// Two-level grid barrier: 16 groups x 16 arrivals, then 16 -> root.
// All 256 blocks co-resident (2/SM by launch_bounds, smem 34.3KB*2 < 228KB).
__device__ __forceinline__ void grid_barrier() {
    __syncthreads();
    if (threadIdx.x == 0) {
        __threadfence();
        unsigned gen = g_bar_gen;
        unsigned r = atomicAdd(&g_cnt1[(blockIdx.x >> 4) * 32], 1u);
        if (r == 15) {
            unsigned r2 = atomicAdd(&g_cnt2, 1u);
            if (r2 == 15) {
                g_cnt2 = 0;
#pragma unroll
                for (int i = 0; i < 16; i++) g_cnt1[i * 32] = 0;
                __threadfence();            // resets visible before release
                g_bar_gen = gen + 1;
            } else {
                while (g_bar_gen == gen) {}
            }
        } else {
            while (g_bar_gen == gen) {}
        }
        __threadfence();
    }
    __syncthreads();
}

// Distributed BN finalize: every block computes 24 folded affine consts itself.
__device__ __forceinline__ void compute_bn24(const float* __restrict__ ps,
                                             const float* __restrict__ pq,
                                             int np, float invM,
                                             const float* __restrict__ gamma,
                                             const float* __restrict__ beta,
                                             float* s_a, float* s_c, int t) {
    if (t < 192) {
        int c = t >> 3, g = t & 7;
        float s = 0.f, q = 0.f;
        for (int i = g; i < np; i += 8) { s += ps[c * np + i]; q += pq[c * np + i]; }
#pragma unroll
        for (int o = 4; o > 0; o >>= 1) {
            s += __shfl_down_sync(0xffffffffu, s, o, 8);
            q += __shfl_down_sync(0xffffffffu, q, o, 8);
        }
        if (g == 0) {
            float mean = s * invM;
            float var  = q * invM - mean * mean;
            float a    = gamma[c] * rsqrtf(var + 1e-5f);
            s_a[c] = a;
            s_c[c] = beta[c] - mean * a;
        }
    }
}

// ------------------------- fused persistent kernel -------------------------
__global__ void __launch_bounds__(256, 2) fused_kernel(
    const float* __restrict__ image, const float* __restrict__ w1,
    const float* __restrict__ bn1_g, const float* __restrict__ bn1_b,
    const float* __restrict__ w2, const float* __restrict__ bn2_g,
    const float* __restrict__ bn2_b, const float* __restrict__ ques,
    const float* __restrict__ w_rel, const float* __restrict__ b_rel,
    const float* __restrict__ w_fc1, const float* __restrict__ b_fc1,
    const float* __restrict__ w_fc2, const float* __restrict__ b_fc2,
    float* __restrict__ out) {

    __shared__ __align__(16) float smem[8576];
    const int bid = blockIdx.x;
    const int t = threadIdx.x;
    const int warp = t >> 5, lane = t & 31;

    // ============================ PHASE 1: conv1 ============================
    // 256 blocks: n = bid>>3, quarter q = (bid>>1)&3 (8 out rows), cb = (bid&1)*12
    {
        const int n = bid >> 3;
        const int q = (bid >> 1) & 3;
        const int cb = (bid & 1) * 12;
        float* s_in = smem;                       // [3][17][65]  (3315)
        float* s_w  = smem + 3328;                // [(ci*3+kh)][40] (360)
        float* s_rd = smem + 3696;                // [12][8][2]

        for (int idx = t; idx < 3 * 17 * 64; idx += 256) {
            int c   = idx / 1088;
            int rem = idx - c * 1088;
            int r   = rem >> 6;
            int w   = rem & 63;
            int hg  = 16 * q - 1 + r;
            float v = 0.f;
            if (hg >= 0) v = image[((n * 3 + c) * 64 + hg) * 64 + w];
            s_in[c * 1105 + r * 65 + w + 1] = v;
        }
        if (t < 51) s_in[(t / 17) * 1105 + (t % 17) * 65] = 0.f;
        for (int idx = t; idx < 324; idx += 256) {
            int co = idx / 27;
            int rem = idx % 27;
            int ci = rem / 9, kh = (rem % 9) / 3, kw = rem % 3;
            s_w[(ci * 3 + kh) * 40 + co * 3 + kw] = w1[(cb + co) * 27 + rem];
        }
        __syncthreads();

        const int r = t >> 5, wo = t & 31;   // 8 rows x 32 cols, 1 px/thread
        float acc[12];
#pragma unroll
        for (int co = 0; co < 12; co++) acc[co] = 0.f;

#pragma unroll 1
        for (int ci = 0; ci < 3; ci++) {
#pragma unroll
            for (int kh = 0; kh < 3; kh++) {
                const float* ip = &s_in[ci * 1105 + (2 * r + kh) * 65 + 2 * wo];
                float v0 = ip[0], v1 = ip[1], v2 = ip[2];
                const float4* wp = reinterpret_cast<const float4*>(&s_w[(ci * 3 + kh) * 40]);
#pragma unroll
                for (int c4 = 0; c4 < 3; c4++) {
                    float4 a = wp[c4 * 3], b = wp[c4 * 3 + 1], c = wp[c4 * 3 + 2];
                    acc[4 * c4 + 0] += v0 * a.x + v1 * a.y + v2 * a.z;
                    acc[4 * c4 + 1] += v0 * a.w + v1 * b.x + v2 * b.y;
                    acc[4 * c4 + 2] += v0 * b.z + v1 * b.w + v2 * c.x;
                    acc[4 * c4 + 3] += v0 * c.y + v1 * c.z + v2 * c.w;
                }
            }
        }

#pragma unroll
        for (int co = 0; co < 12; co++)
            g_y1[((n * 24 + cb + co) * 32 + q * 8 + r) * 32 + wo] = acc[co];

#pragma unroll
        for (int co = 0; co < 12; co++) {
            float rs = warp_sum(acc[co]);
            float rq = warp_sum(acc[co] * acc[co]);
            if (lane == 0) { s_rd[co * 16 + warp * 2] = rs; s_rd[co * 16 + warp * 2 + 1] = rq; }
        }
        __syncthreads();
        if (t < 12) {
            float s = 0.f, qq = 0.f;
#pragma unroll
            for (int w = 0; w < 8; w++) { s += s_rd[t * 16 + w * 2]; qq += s_rd[t * 16 + w * 2 + 1]; }
            g_part1s[(cb + t) * 128 + n * 4 + q] = s;
            g_part1q[(cb + t) * 128 + n * 4 + q] = qq;
        }
    }

    grid_barrier();

    // ============================ PHASE 2: conv2 ============================
    // 256 blocks: n = bid>>3, co-group cb = ((bid>>1)&3)*6, half = bid&1.
    // Each block: out rows [8*half, 8*half+8) x 16 cols x 6 channels.
    // t&127 -> pixel (r = (t&127)>>4 in 0..7, wo = t&15); hh = t>>7 -> ch triple.
    {
        const int n = bid >> 3;
        const int cb = ((bid >> 1) & 3) * 6;
        const int half = bid & 1;
        float* s_in = smem;                       // [12][17][33] (6732)
        float* s_w  = smem + 6736;                // [72][24] (1728)
        float* s_a  = smem + 8464;
        float* s_c  = smem + 8488;
        float* s_rd = smem + 8512;                // [6][4][2]

        compute_bn24(g_part1s, g_part1q, 128, 1.f / 32768.f, bn1_g, bn1_b, s_a, s_c, t);

        // stage all weights once: dst [(ci*3+kh)*24 + hh*12 + c3*3 + kw]
        for (int idx = t; idx < 1296; idx += 256) {
            int ci = idx / 54;
            int rem = idx % 54;
            int kh = rem / 18;
            int ch = (rem % 18) / 3;
            int kw = rem % 3;
            s_w[(ci * 3 + kh) * 24 + (ch / 3) * 12 + (ch % 3) * 3 + kw] =
                w2[((cb + ch) * 24 + ci) * 9 + kh * 3 + kw];
        }

        const int px = t & 127;
        const int r = px >> 4, wo = px & 15;
        const int hh = t >> 7;
        float acc0 = 0.f, acc1 = 0.f, acc2 = 0.f;

#pragma unroll 1
        for (int ph = 0; ph < 2; ph++) {
            const int cc = ph * 12;
            __syncthreads();   // first iter: weights+BN consts; later: s_in reuse
            // stage y1 rows 16*half-1 .. 16*half+15 for 12 channels, BN+ReLU
            for (int idx = t; idx < 12 * 17 * 32; idx += 256) {
                int ci  = idx / 544;
                int rem = idx - ci * 544;
                int rr  = rem >> 5, w = rem & 31;
                int row = 16 * half - 1 + rr;
                float f = 0.f;
                if (row >= 0) {
                    float y = g_y1[((n * 24 + cc + ci) * 32 + row) * 32 + w];
                    f = fmaxf(fmaf(s_a[cc + ci], y, s_c[cc + ci]), 0.f);
                }
                s_in[ci * 561 + rr * 33 + w + 1] = f;
            }
            if (t < 204) s_in[(t / 17) * 561 + (t % 17) * 33] = 0.f;  // col 0 pad
            __syncthreads();

#pragma unroll 1
            for (int ci = 0; ci < 12; ci++) {
#pragma unroll
                for (int kh = 0; kh < 3; kh++) {
                    const float* ip = &s_in[ci * 561 + (2 * r + kh) * 33 + 2 * wo];
                    float v0 = ip[0], v1 = ip[1], v2 = ip[2];
                    const float* wb = &s_w[((cc + ci) * 3 + kh) * 24 + hh * 12];
                    float4 wa = *reinterpret_cast<const float4*>(wb);
                    float4 wc = *reinterpret_cast<const float4*>(wb + 4);
                    float w8 = wb[8];
                    acc0 += v0 * wa.x + v1 * wa.y + v2 * wa.z;
                    acc1 += v0 * wa.w + v1 * wc.x + v2 * wc.y;
                    acc2 += v0 * wc.z + v1 * wc.w + v2 * w8;
                }
            }
        }

        const int ho = half * 8 + r;
        g_y2[((n * 24 + cb + hh * 3 + 0) * 16 + ho) * 16 + wo] = acc0;
        g_y2[((n * 24 + cb + hh * 3 + 1) * 16 + ho) * 16 + wo] = acc1;
        g_y2[((n * 24 + cb + hh * 3 + 2) * 16 + ho) * 16 + wo] = acc2;

        // per-channel partial sums over this block's 128 px (4 warps per triple)
        float av[3] = {acc0, acc1, acc2};
#pragma unroll
        for (int c3 = 0; c3 < 3; c3++) {
            float rs = warp_sum(av[c3]);
            float rq = warp_sum(av[c3] * av[c3]);
            if (lane == 0) {
                int ch = hh * 3 + c3, w4 = warp & 3;
                s_rd[ch * 8 + w4 * 2] = rs;
                s_rd[ch * 8 + w4 * 2 + 1] = rq;
            }
        }
        __syncthreads();
        if (t < 6) {
            float s = 0.f, qq = 0.f;
#pragma unroll
            for (int w = 0; w < 4; w++) { s += s_rd[t * 8 + w * 2]; qq += s_rd[t * 8 + w * 2 + 1]; }
            g_part2s[(cb + t) * 64 + n * 2 + half] = s;
            g_part2q[(cb + t) * 64 + n * 2 + half] = qq;
        }
    }

    grid_barrier();

    // ============================ PHASE 3: head ============================
    // 256 blocks: n = bid>>3, chunk = bid&7 (128 fc1 outputs each).
    // Final per-n reduce done by the 8th finisher via atomic ticket (no barrier).
    {
        const int n = bid >> 3;
        const int chunk = bid & 7;
        float* s_q     = smem;            // 128
        float* s_a2    = smem + 128;      // 24
        float* s_c2    = smem + 152;      // 24
        float* s_part  = smem + 176;      // 24*8
        float* s_s     = smem + 368;      // 26 (pad 32)
        float* s_r     = smem + 400;      // 128
        float* s_hpart = smem + 528;      // 256
        float* s_o     = smem + 784;      // 8

        compute_bn24(g_part2s, g_part2q, 64, 1.f / 8192.f, bn2_g, bn2_b, s_a2, s_c2, t);
        if (t >= 192) {
            int j = t - 192;
            s_q[j * 2]     = ques[n * 128 + j * 2];
            s_q[j * 2 + 1] = ques[n * 128 + j * 2 + 1];
        }
        __syncthreads();

        // spatial sums of relu(bn2(y2)) -> s[0..23]; coord sums ~0 -> 0
        if (t < 192) {
            int c = t >> 3, g = t & 7;
            const float* yp = &g_y2[(n * 24 + c) * 256 + g * 32];
            float a = s_a2[c], cc = s_c2[c];
            float acc = 0.f;
#pragma unroll
            for (int i = 0; i < 32; i++) acc += fmaxf(fmaf(a, yp[i], cc), 0.f);
            s_part[c * 8 + g] = acc;
        }
        __syncthreads();
        if (t < 26) {
            float s = 0.f;
            if (t < 24) {
#pragma unroll
                for (int g = 0; g < 8; g++) s += s_part[t * 8 + g];
            }
            s_s[t] = s;
        }
        __syncthreads();

        // relations[j] = 256 * s.(Wi+Wj)[:,j] + 65536 * (q.Wq[:,j] + b_rel[j])
        if (t < 128) {
            const int j = t;
            float r1 = 0.f;
#pragma unroll
            for (int k = 0; k < 26; k++)
                r1 += s_s[k] * (w_rel[k * 128 + j] + w_rel[(26 + k) * 128 + j]);
            float r2 = b_rel[j];
#pragma unroll 8
            for (int q = 0; q < 128; q++)
                r2 = fmaf(s_q[q], w_rel[(52 + q) * 128 + j], r2);
            s_r[j] = 256.f * r1 + 65536.f * r2;
        }
        __syncthreads();

        // fc1 chunk: outputs chunk*128+jj, k split in halves across thread pairs
        {
            const int jj = t & 127, h = t >> 7;
            const int j = chunk * 128 + jj;
            float acc = (h == 0) ? b_fc1[j] : 0.f;
            const float* wp = &w_fc1[(h * 64) * 1024 + j];
            const float* rp = &s_r[h * 64];
#pragma unroll 8
            for (int k = 0; k < 64; k++)
                acc = fmaf(rp[k], wp[k * 1024], acc);
            s_hpart[t] = acc;
        }
        __syncthreads();
        // relu + partial fc2 over this chunk's 128 h values
        {
            float p0 = 0.f, p1 = 0.f;
            if (t < 128) {
                float hv = fmaxf(s_hpart[t] + s_hpart[t + 128], 0.f);
                const int j = chunk * 128 + t;
                p0 = hv * w_fc2[j * 2];
                p1 = hv * w_fc2[j * 2 + 1];
            }
            p0 = warp_sum(p0);
            p1 = warp_sum(p1);
            if (lane == 0 && warp < 4) { s_o[warp * 2] = p0; s_o[warp * 2 + 1] = p1; }
        }
        __syncthreads();
        if (t == 0) {
            float o0 = 0.f, o1 = 0.f;
#pragma unroll
            for (int w = 0; w < 4; w++) { o0 += s_o[w * 2]; o1 += s_o[w * 2 + 1]; }
            g_hpart[(n * 8 + chunk) * 2 + 0] = o0;
            g_hpart[(n * 8 + chunk) * 2 + 1] = o1;
            __threadfence();
            unsigned r = atomicAdd(&g_done[n], 1u);
            if (r == 7) {                      // last chunk for this n: finish
                __threadfence();
                float f0 = b_fc2[0], f1 = b_fc2[1];
#pragma unroll
                for (int c = 0; c < 8; c++) {
                    f0 += g_hpart[(n * 8 + c) * 2 + 0];
                    f1 += g_hpart[(n * 8 + c) * 2 + 1];
                }
                out[n * 2 + 0] = f0;
                out[n * 2 + 1] = f1;
                g_done[n] = 0;                 // self-reset for graph replay
            }
        }
    }
}

// ---------------- launch ----------------
extern "C" void kernel_launch(void* const* d_in, const int* in_sizes, int n_in,
                              void* d_out, int out_size) {
    (void)in_sizes; (void)n_in; (void)out_size;
    const float* image   = (const float*)d_in[0];
    const float* ques    = (const float*)d_in[1];
    const float* conv1_w = (const float*)d_in[2];
    const float* bn1_g   = (const float*)d_in[4];
    const float* bn1_b   = (const float*)d_in[5];
    const float* conv2_w = (const float*)d_in[6];
    const float* bn2_g   = (const float*)d_in[8];
    const float* bn2_b   = (const float*)d_in[9];
    const float* w_rel   = (const float*)d_in[10];
    const float* b_rel   = (const float*)d_in[11];
    const float* w_fc1   = (const float*)d_in[12];
    const float* b_fc1   = (const float*)d_in[13];
    const float* w_fc2   = (const float*)d_in[14];
    const float* b_fc2   = (const float*)d_in[15];
    float* out = (float*)d_out;

    fused_kernel<<<NBLOCKS, 256>>>(image, conv1_w, bn1_g, bn1_b,
                                   conv2_w, bn2_g, bn2_b,
                                   ques, w_rel, b_rel,
                                   w_fc1, b_fc1, w_fc2, b_fc2, out);
}

// round 7
// speedup vs baseline: 1.0007x; 1.0007x over previous
#include <cuda_runtime.h>

// ---------------- scratch (static device globals; no allocation) ----------------
__device__ float g_y1[32 * 24 * 32 * 32];   // conv1 raw output (pre-BN)
__device__ float g_y2[32 * 24 * 16 * 16];   // conv2 raw output (pre-BN)
__device__ float g_part1s[24 * 128];        // conv1 per-block channel sums
__device__ float g_part1q[24 * 128];
__device__ float g_part2s[24 * 64];         // conv2: key = n*2+half
__device__ float g_part2q[24 * 64];
__device__ float g_hpart[32 * 8 * 2];       // per-(n,chunk) fc2 partials
__device__ unsigned g_done[32];             // per-n ticket, zero-init, self-reset
__device__ unsigned g_cnt1[16 * 32];        // group counters, padded to 128B lines
__device__ unsigned g_cnt2;                 // root counter
__device__ volatile unsigned g_bar_gen;

#define NBLOCKS 256

__device__ __forceinline__ float warp_sum(float v) {
#pragma unroll
    for (int o = 16; o > 0; o >>= 1) v += __shfl_down_sync(0xffffffffu, v, o);
    return v;
}

// Two-level grid barrier: 16 groups x 16 arrivals, then 16 -> root.
// All 256 blocks co-resident (2/SM by launch_bounds, smem 34.3KB*2 < 228KB).
__device__ __forceinline__ void grid_barrier() {
    __syncthreads();
    if (threadIdx.x == 0) {
        __threadfence();
        unsigned gen = g_bar_gen;
        unsigned r = atomicAdd(&g_cnt1[(blockIdx.x >> 4) * 32], 1u);
        if (r == 15) {
            unsigned r2 = atomicAdd(&g_cnt2, 1u);
            if (r2 == 15) {
                g_cnt2 = 0;
#pragma unroll
                for (int i = 0; i < 16; i++) g_cnt1[i * 32] = 0;
                __threadfence();            // resets visible before release
                g_bar_gen = gen + 1;
            } else {
                while (g_bar_gen == gen) {}
            }
        } else {
            while (g_bar_gen == gen) {}
        }
        __threadfence();
    }
    __syncthreads();
}

// Distributed BN finalize: every block computes 24 folded affine consts itself.
__device__ __forceinline__ void compute_bn24(const float* __restrict__ ps,
                                             const float* __restrict__ pq,
                                             int np, float invM,
                                             const float* __restrict__ gamma,
                                             const float* __restrict__ beta,
                                             float* s_a, float* s_c, int t) {
    if (t < 192) {
        int c = t >> 3, g = t & 7;
        float s = 0.f, q = 0.f;
        for (int i = g; i < np; i += 8) { s += ps[c * np + i]; q += pq[c * np + i]; }
#pragma unroll
        for (int o = 4; o > 0; o >>= 1) {
            s += __shfl_down_sync(0xffffffffu, s, o, 8);
            q += __shfl_down_sync(0xffffffffu, q, o, 8);
        }
        if (g == 0) {
            float mean = s * invM;
            float var  = q * invM - mean * mean;
            float a    = gamma[c] * rsqrtf(var + 1e-5f);
            s_a[c] = a;
            s_c[c] = beta[c] - mean * a;
        }
    }
}

// ------------------------- fused persistent kernel -------------------------
__global__ void __launch_bounds__(256, 2) fused_kernel(
    const float* __restrict__ image, const float* __restrict__ w1,
    const float* __restrict__ bn1_g, const float* __restrict__ bn1_b,
    const float* __restrict__ w2, const float* __restrict__ bn2_g,
    const float* __restrict__ bn2_b, const float* __restrict__ ques,
    const float* __restrict__ w_rel, const float* __restrict__ b_rel,
    const float* __restrict__ w_fc1, const float* __restrict__ b_fc1,
    const float* __restrict__ w_fc2, const float* __restrict__ b_fc2,
    float* __restrict__ out) {

    __shared__ __align__(16) float smem[8576];
    const int bid = blockIdx.x;
    const int t = threadIdx.x;
    const int warp = t >> 5, lane = t & 31;

    // ============================ PHASE 1: conv1 ============================
    // 256 blocks: n = bid>>3, quarter q = (bid>>1)&3 (8 out rows), cb = (bid&1)*12
    {
        const int n = bid >> 3;
        const int q = (bid >> 1) & 3;
        const int cb = (bid & 1) * 12;
        float* s_in = smem;                       // [3][17][65]  (3315)
        float* s_w  = smem + 3328;                // [(ci*3+kh)][40] (360)
        float* s_rd = smem + 3696;                // [12][8][2]

        for (int idx = t; idx < 3 * 17 * 64; idx += 256) {
            int c   = idx / 1088;
            int rem = idx - c * 1088;
            int r   = rem >> 6;
            int w   = rem & 63;
            int hg  = 16 * q - 1 + r;
            float v = 0.f;
            if (hg >= 0) v = image[((n * 3 + c) * 64 + hg) * 64 + w];
            s_in[c * 1105 + r * 65 + w + 1] = v;
        }
        if (t < 51) s_in[(t / 17) * 1105 + (t % 17) * 65] = 0.f;
        for (int idx = t; idx < 324; idx += 256) {
            int co = idx / 27;
            int rem = idx % 27;
            int ci = rem / 9, kh = (rem % 9) / 3, kw = rem % 3;
            s_w[(ci * 3 + kh) * 40 + co * 3 + kw] = w1[(cb + co) * 27 + rem];
        }
        __syncthreads();

        const int r = t >> 5, wo = t & 31;   // 8 rows x 32 cols, 1 px/thread
        float acc[12];
#pragma unroll
        for (int co = 0; co < 12; co++) acc[co] = 0.f;

#pragma unroll 1
        for (int ci = 0; ci < 3; ci++) {
#pragma unroll
            for (int kh = 0; kh < 3; kh++) {
                const float* ip = &s_in[ci * 1105 + (2 * r + kh) * 65 + 2 * wo];
                float v0 = ip[0], v1 = ip[1], v2 = ip[2];
                const float4* wp = reinterpret_cast<const float4*>(&s_w[(ci * 3 + kh) * 40]);
#pragma unroll
                for (int c4 = 0; c4 < 3; c4++) {
                    float4 a = wp[c4 * 3], b = wp[c4 * 3 + 1], c = wp[c4 * 3 + 2];
                    acc[4 * c4 + 0] += v0 * a.x + v1 * a.y + v2 * a.z;
                    acc[4 * c4 + 1] += v0 * a.w + v1 * b.x + v2 * b.y;
                    acc[4 * c4 + 2] += v0 * b.z + v1 * b.w + v2 * c.x;
                    acc[4 * c4 + 3] += v0 * c.y + v1 * c.z + v2 * c.w;
                }
            }
        }

#pragma unroll
        for (int co = 0; co < 12; co++)
            g_y1[((n * 24 + cb + co) * 32 + q * 8 + r) * 32 + wo] = acc[co];

#pragma unroll
        for (int co = 0; co < 12; co++) {
            float rs = warp_sum(acc[co]);
            float rq = warp_sum(acc[co] * acc[co]);
            if (lane == 0) { s_rd[co * 16 + warp * 2] = rs; s_rd[co * 16 + warp * 2 + 1] = rq; }
        }
        __syncthreads();
        if (t < 12) {
            float s = 0.f, qq = 0.f;
#pragma unroll
            for (int w = 0; w < 8; w++) { s += s_rd[t * 16 + w * 2]; qq += s_rd[t * 16 + w * 2 + 1]; }
            g_part1s[(cb + t) * 128 + n * 4 + q] = s;
            g_part1q[(cb + t) * 128 + n * 4 + q] = qq;
        }
    }

    grid_barrier();

    // ============================ PHASE 2: conv2 ============================
    // 256 blocks: n = bid>>3, co-group cb = ((bid>>1)&3)*6, half = bid&1.
    // Each block: out rows [8*half, 8*half+8) x 16 cols x 6 channels.
    // t&127 -> pixel (r = (t&127)>>4 in 0..7, wo = t&15); hh = t>>7 -> ch triple.
    {
        const int n = bid >> 3;
        const int cb = ((bid >> 1) & 3) * 6;
        const int half = bid & 1;
        float* s_in = smem;                       // [12][17][33] (6732)
        float* s_w  = smem + 6736;                // [72][24] (1728)
        float* s_a  = smem + 8464;
        float* s_c  = smem + 8488;
        float* s_rd = smem + 8512;                // [6][4][2]

        compute_bn24(g_part1s, g_part1q, 128, 1.f / 32768.f, bn1_g, bn1_b, s_a, s_c, t);

        // stage all weights once: dst [(ci*3+kh)*24 + hh*12 + c3*3 + kw]
        for (int idx = t; idx < 1296; idx += 256) {
            int ci = idx / 54;
            int rem = idx % 54;
            int kh = rem / 18;
            int ch = (rem % 18) / 3;
            int kw = rem % 3;
            s_w[(ci * 3 + kh) * 24 + (ch / 3) * 12 + (ch % 3) * 3 + kw] =
                w2[((cb + ch) * 24 + ci) * 9 + kh * 3 + kw];
        }

        const int px = t & 127;
        const int r = px >> 4, wo = px & 15;
        const int hh = t >> 7;
        float acc0 = 0.f, acc1 = 0.f, acc2 = 0.f;

#pragma unroll 1
        for (int ph = 0; ph < 2; ph++) {
            const int cc = ph * 12;
            __syncthreads();   // first iter: weights+BN consts; later: s_in reuse
            // stage y1 rows 16*half-1 .. 16*half+15 for 12 channels, BN+ReLU
            for (int idx = t; idx < 12 * 17 * 32; idx += 256) {
                int ci  = idx / 544;
                int rem = idx - ci * 544;
                int rr  = rem >> 5, w = rem & 31;
                int row = 16 * half - 1 + rr;
                float f = 0.f;
                if (row >= 0) {
                    float y = g_y1[((n * 24 + cc + ci) * 32 + row) * 32 + w];
                    f = fmaxf(fmaf(s_a[cc + ci], y, s_c[cc + ci]), 0.f);
                }
                s_in[ci * 561 + rr * 33 + w + 1] = f;
            }
            if (t < 204) s_in[(t / 17) * 561 + (t % 17) * 33] = 0.f;  // col 0 pad
            __syncthreads();

#pragma unroll 1
            for (int ci = 0; ci < 12; ci++) {
#pragma unroll
                for (int kh = 0; kh < 3; kh++) {
                    const float* ip = &s_in[ci * 561 + (2 * r + kh) * 33 + 2 * wo];
                    float v0 = ip[0], v1 = ip[1], v2 = ip[2];
                    const float* wb = &s_w[((cc + ci) * 3 + kh) * 24 + hh * 12];
                    float4 wa = *reinterpret_cast<const float4*>(wb);
                    float4 wc = *reinterpret_cast<const float4*>(wb + 4);
                    float w8 = wb[8];
                    acc0 += v0 * wa.x + v1 * wa.y + v2 * wa.z;
                    acc1 += v0 * wa.w + v1 * wc.x + v2 * wc.y;
                    acc2 += v0 * wc.z + v1 * wc.w + v2 * w8;
                }
            }
        }

        const int ho = half * 8 + r;
        g_y2[((n * 24 + cb + hh * 3 + 0) * 16 + ho) * 16 + wo] = acc0;
        g_y2[((n * 24 + cb + hh * 3 + 1) * 16 + ho) * 16 + wo] = acc1;
        g_y2[((n * 24 + cb + hh * 3 + 2) * 16 + ho) * 16 + wo] = acc2;

        // per-channel partial sums over this block's 128 px (4 warps per triple)
        float av[3] = {acc0, acc1, acc2};
#pragma unroll
        for (int c3 = 0; c3 < 3; c3++) {
            float rs = warp_sum(av[c3]);
            float rq = warp_sum(av[c3] * av[c3]);
            if (lane == 0) {
                int ch = hh * 3 + c3, w4 = warp & 3;
                s_rd[ch * 8 + w4 * 2] = rs;
                s_rd[ch * 8 + w4 * 2 + 1] = rq;
            }
        }
        __syncthreads();
        if (t < 6) {
            float s = 0.f, qq = 0.f;
#pragma unroll
            for (int w = 0; w < 4; w++) { s += s_rd[t * 8 + w * 2]; qq += s_rd[t * 8 + w * 2 + 1]; }
            g_part2s[(cb + t) * 64 + n * 2 + half] = s;
            g_part2q[(cb + t) * 64 + n * 2 + half] = qq;
        }
    }

    grid_barrier();

    // ============================ PHASE 3: head ============================
    // 256 blocks: n = bid>>3, chunk = bid&7 (128 fc1 outputs each).
    // Final per-n reduce done by the 8th finisher via atomic ticket (no barrier).
    {
        const int n = bid >> 3;
        const int chunk = bid & 7;
        float* s_q     = smem;            // 128
        float* s_a2    = smem + 128;      // 24
        float* s_c2    = smem + 152;      // 24
        float* s_part  = smem + 176;      // 24*8
        float* s_s     = smem + 368;      // 26 (pad 32)
        float* s_r     = smem + 400;      // 128
        float* s_hpart = smem + 528;      // 256
        float* s_o     = smem + 784;      // 8

        compute_bn24(g_part2s, g_part2q, 64, 1.f / 8192.f, bn2_g, bn2_b, s_a2, s_c2, t);
        if (t >= 192) {
            int j = t - 192;
            s_q[j * 2]     = ques[n * 128 + j * 2];
            s_q[j * 2 + 1] = ques[n * 128 + j * 2 + 1];
        }
        __syncthreads();

        // spatial sums of relu(bn2(y2)) -> s[0..23]; coord sums ~0 -> 0
        if (t < 192) {
            int c = t >> 3, g = t & 7;
            const float* yp = &g_y2[(n * 24 + c) * 256 + g * 32];
            float a = s_a2[c], cc = s_c2[c];
            float acc = 0.f;
#pragma unroll
            for (int i = 0; i < 32; i++) acc += fmaxf(fmaf(a, yp[i], cc), 0.f);
            s_part[c * 8 + g] = acc;
        }
        __syncthreads();
        if (t < 26) {
            float s = 0.f;
            if (t < 24) {
#pragma unroll
                for (int g = 0; g < 8; g++) s += s_part[t * 8 + g];
            }
            s_s[t] = s;
        }
        __syncthreads();

        // relations[j] = 256 * s.(Wi+Wj)[:,j] + 65536 * (q.Wq[:,j] + b_rel[j])
        if (t < 128) {
            const int j = t;
            float r1 = 0.f;
#pragma unroll
            for (int k = 0; k < 26; k++)
                r1 += s_s[k] * (w_rel[k * 128 + j] + w_rel[(26 + k) * 128 + j]);
            float r2 = b_rel[j];
#pragma unroll 8
            for (int q = 0; q < 128; q++)
                r2 = fmaf(s_q[q], w_rel[(52 + q) * 128 + j], r2);
            s_r[j] = 256.f * r1 + 65536.f * r2;
        }
        __syncthreads();

        // fc1 chunk: outputs chunk*128+jj, k split in halves across thread pairs
        {
            const int jj = t & 127, h = t >> 7;
            const int j = chunk * 128 + jj;
            float acc = (h == 0) ? b_fc1[j] : 0.f;
            const float* wp = &w_fc1[(h * 64) * 1024 + j];
            const float* rp = &s_r[h * 64];
#pragma unroll 8
            for (int k = 0; k < 64; k++)
                acc = fmaf(rp[k], wp[k * 1024], acc);
            s_hpart[t] = acc;
        }
        __syncthreads();
        // relu + partial fc2 over this chunk's 128 h values
        {
            float p0 = 0.f, p1 = 0.f;
            if (t < 128) {
                float hv = fmaxf(s_hpart[t] + s_hpart[t + 128], 0.f);
                const int j = chunk * 128 + t;
                p0 = hv * w_fc2[j * 2];
                p1 = hv * w_fc2[j * 2 + 1];
            }
            p0 = warp_sum(p0);
            p1 = warp_sum(p1);
            if (lane == 0 && warp < 4) { s_o[warp * 2] = p0; s_o[warp * 2 + 1] = p1; }
        }
        __syncthreads();
        if (t == 0) {
            float o0 = 0.f, o1 = 0.f;
#pragma unroll
            for (int w = 0; w < 4; w++) { o0 += s_o[w * 2]; o1 += s_o[w * 2 + 1]; }
            g_hpart[(n * 8 + chunk) * 2 + 0] = o0;
            g_hpart[(n * 8 + chunk) * 2 + 1] = o1;
            __threadfence();
            unsigned r = atomicAdd(&g_done[n], 1u);
            if (r == 7) {                      // last chunk for this n: finish
                __threadfence();
                float f0 = b_fc2[0], f1 = b_fc2[1];
#pragma unroll
                for (int c = 0; c < 8; c++) {
                    f0 += g_hpart[(n * 8 + c) * 2 + 0];
                    f1 += g_hpart[(n * 8 + c) * 2 + 1];
                }
                out[n * 2 + 0] = f0;
                out[n * 2 + 1] = f1;
                g_done[n] = 0;                 // self-reset for graph replay
            }
        }
    }
}

// ---------------- launch ----------------
extern "C" void kernel_launch(void* const* d_in, const int* in_sizes, int n_in,
                              void* d_out, int out_size) {
    (void)in_sizes; (void)n_in; (void)out_size;
    const float* image   = (const float*)d_in[0];
    const float* ques    = (const float*)d_in[1];
    const float* conv1_w = (const float*)d_in[2];
    const float* bn1_g   = (const float*)d_in[4];
    const float* bn1_b   = (const float*)d_in[5];
    const float* conv2_w = (const float*)d_in[6];
    const float* bn2_g   = (const float*)d_in[8];
    const float* bn2_b   = (const float*)d_in[9];
    const float* w_rel   = (const float*)d_in[10];
    const float* b_rel   = (const float*)d_in[11];
    const float* w_fc1   = (const float*)d_in[12];
    const float* b_fc1   = (const float*)d_in[13];
    const float* w_fc2   = (const float*)d_in[14];
    const float* b_fc2   = (const float*)d_in[15];
    float* out = (float*)d_out;

    fused_kernel<<<NBLOCKS, 256>>>(image, conv1_w, bn1_g, bn1_b,
                                   conv2_w, bn2_g, bn2_b,
                                   ques, w_rel, b_rel,
                                   w_fc1, b_fc1, w_fc2, b_fc2, out);
}

// round 8
// speedup vs baseline: 1.2713x; 1.2704x over previous
#include <cuda_runtime.h>

// ---------------- scratch ----------------
__device__ float g_y1[32 * 24 * 32 * 32];
__device__ float g_y2[32 * 24 * 16 * 16];
__device__ float g_p1s[24 * 64];          // key n*2+h16
__device__ float g_p1q[24 * 64];
__device__ float g_p2s[24 * 64];          // key n*2+half
__device__ float g_p2q[24 * 64];
__device__ float g_hpart[32 * 4 * 2];
__device__ unsigned g_done[32];           // zero-init, self-reset
__device__ unsigned g_cnt1[8 * 32];       // padded group counters
__device__ unsigned g_cnt2;
__device__ volatile unsigned g_bar_gen;

#define NB 128

__device__ __forceinline__ float warp_sum(float v) {
#pragma unroll
    for (int o = 16; o > 0; o >>= 1) v += __shfl_down_sync(0xffffffffu, v, o);
    return v;
}

// Two-level grid barrier: 8 groups x 16, then 8 -> root. 128 blocks, 1/SM.
__device__ __forceinline__ void grid_barrier() {
    __syncthreads();
    if (threadIdx.x == 0) {
        __threadfence();
        unsigned gen = g_bar_gen;
        unsigned r = atomicAdd(&g_cnt1[(blockIdx.x >> 4) * 32], 1u);
        if (r == 15) {
            unsigned r2 = atomicAdd(&g_cnt2, 1u);
            if (r2 == 7) {
                g_cnt2 = 0;
#pragma unroll
                for (int i = 0; i < 8; i++) g_cnt1[i * 32] = 0;
                __threadfence();
                g_bar_gen = gen + 1;
            } else {
                while (g_bar_gen == gen) {}
            }
        } else {
            while (g_bar_gen == gen) {}
        }
        __threadfence();
    }
    __syncthreads();
}

__device__ __forceinline__ void compute_bn24(const float* __restrict__ ps,
                                             const float* __restrict__ pq,
                                             float invM,
                                             const float* __restrict__ gamma,
                                             const float* __restrict__ beta,
                                             float* s_a, float* s_c, int t) {
    if (t < 192) {
        int c = t >> 3, g = t & 7;
        float s = 0.f, q = 0.f;
        for (int i = g; i < 64; i += 8) { s += ps[c * 64 + i]; q += pq[c * 64 + i]; }
#pragma unroll
        for (int o = 4; o > 0; o >>= 1) {
            s += __shfl_down_sync(0xffffffffu, s, o, 8);
            q += __shfl_down_sync(0xffffffffu, q, o, 8);
        }
        if (g == 0) {
            float mean = s * invM;
            float var  = q * invM - mean * mean;
            float a    = gamma[c] * rsqrtf(var + 1e-5f);
            s_a[c] = a;
            s_c[c] = beta[c] - mean * a;
        }
    }
}

// smem offsets (floats)
#define EV1 0            // [3][33][32]  3168
#define OD1 3168         // [3][33][33]  3267  (col0 = zero pad)
#define W1  6448         // [(ci*3+kh)*3+kw][12] 324
#define RD1 6784         // [12][16][2]  384
#define EV2 0            // [12][17][16] 3264
#define OD2 3264         // [12][17][17] 3468  (col0 pad)
#define W2  6736         // [((ci*3+kh)*4+grp)][12] 3456
#define A2  10192
#define C2  10216
#define RD2 10240        // [12][4][2]   96
// head
#define HQ   0
#define HA   128
#define HC   152
#define HP   176         // 24*16 = 384
#define HS   560         // 26 -> pad 32
#define HRA  592         // 128
#define HRB  720         // 512
#define HR   1232        // 128
#define HH   1360        // 512
#define HO   1872        // 16

__global__ void __launch_bounds__(512, 1) fused_kernel(
    const float* __restrict__ image, const float* __restrict__ w1,
    const float* __restrict__ bn1_g, const float* __restrict__ bn1_b,
    const float* __restrict__ w2, const float* __restrict__ bn2_g,
    const float* __restrict__ bn2_b, const float* __restrict__ ques,
    const float* __restrict__ w_rel, const float* __restrict__ b_rel,
    const float* __restrict__ w_fc1, const float* __restrict__ b_fc1,
    const float* __restrict__ w_fc2, const float* __restrict__ b_fc2,
    float* __restrict__ out) {

    __shared__ __align__(16) float sm[10368];
    const int bid = blockIdx.x;
    const int t = threadIdx.x;
    const int warp = t >> 5, lane = t & 31;

    // ============================ PHASE 1: conv1 ============================
    // 128 blocks = 32n x 2 h16 x 2 cg(12co). 512 thr = 16 out rows x 32 cols.
    {
        const int n = bid >> 2;
        const int h16 = (bid >> 1) & 1;
        const int cg = bid & 1;

        // stage input rows 32*h16-1 .. +31 (33), de-interleaved even/odd cols
        for (int idx = t; idx < 3 * 33 * 64; idx += 512) {
            int ci  = idx / 2112;
            int rem = idx - ci * 2112;
            int row = rem >> 6, col = rem & 63;
            int hg  = 32 * h16 - 1 + row;
            float v = (hg >= 0) ? image[((n * 3 + ci) * 64 + hg) * 64 + col] : 0.f;
            if (col & 1) sm[OD1 + ci * 1089 + row * 33 + (col >> 1) + 1] = v;
            else         sm[EV1 + ci * 1056 + row * 32 + (col >> 1)] = v;
        }
        if (t < 99) sm[OD1 + (t / 33) * 1089 + (t % 33) * 33] = 0.f;
        // weights -> [ci][kh][kw][co]
        if (t < 324) {
            int co = t / 27, rem = t % 27;
            int ci = rem / 9, kh = (rem % 9) / 3, kw = rem % 3;
            sm[W1 + ((ci * 3 + kh) * 3 + kw) * 12 + co] = w1[(cg * 12 + co) * 27 + rem];
        }
        __syncthreads();

        const int r = t >> 5, wo = t & 31;   // 1 px/thread
        float acc[12];
#pragma unroll
        for (int co = 0; co < 12; co++) acc[co] = 0.f;

#pragma unroll 1
        for (int ci = 0; ci < 3; ci++) {
#pragma unroll
            for (int kh = 0; kh < 3; kh++) {
                const int rl = 2 * r + kh;
                float vv[3];
                vv[0] = sm[OD1 + ci * 1089 + rl * 33 + wo];       // col 2wo-1
                vv[1] = sm[EV1 + ci * 1056 + rl * 32 + wo];       // col 2wo
                vv[2] = sm[OD1 + ci * 1089 + rl * 33 + wo + 1];   // col 2wo+1
                const float4* wp = reinterpret_cast<const float4*>(&sm[W1 + (ci * 3 + kh) * 36]);
#pragma unroll
                for (int kw = 0; kw < 3; kw++) {
                    float v = vv[kw];
                    float4 a = wp[kw * 3], b = wp[kw * 3 + 1], c = wp[kw * 3 + 2];
                    acc[0] += v * a.x;  acc[1] += v * a.y;  acc[2]  += v * a.z;  acc[3]  += v * a.w;
                    acc[4] += v * b.x;  acc[5] += v * b.y;  acc[6]  += v * b.z;  acc[7]  += v * b.w;
                    acc[8] += v * c.x;  acc[9] += v * c.y;  acc[10] += v * c.z;  acc[11] += v * c.w;
                }
            }
        }

#pragma unroll
        for (int co = 0; co < 12; co++)
            g_y1[((n * 24 + cg * 12 + co) * 32 + h16 * 16 + r) * 32 + wo] = acc[co];

#pragma unroll
        for (int co = 0; co < 12; co++) {
            float rs = warp_sum(acc[co]);
            float rq = warp_sum(acc[co] * acc[co]);
            if (lane == 0) { sm[RD1 + co * 32 + warp * 2] = rs; sm[RD1 + co * 32 + warp * 2 + 1] = rq; }
        }
        __syncthreads();
        if (t < 12) {
            float s = 0.f, q = 0.f;
#pragma unroll
            for (int w = 0; w < 16; w++) { s += sm[RD1 + t * 32 + w * 2]; q += sm[RD1 + t * 32 + w * 2 + 1]; }
            g_p1s[(cg * 12 + t) * 64 + n * 2 + h16] = s;
            g_p1q[(cg * 12 + t) * 64 + n * 2 + h16] = q;
        }
    }

    grid_barrier();

    // ============================ PHASE 2: conv2 ============================
    // 128 blocks = 32n x 2 half(8 rows) x 2 cg(12co).
    // 512 thr: px = t&127 (8x16), grp = t>>7 (0..3) -> 3 co each.
    {
        const int n = bid >> 2;
        const int half = (bid >> 1) & 1;
        const int cg = bid & 1;

        compute_bn24(g_p1s, g_p1q, 1.f / 32768.f, bn1_g, bn1_b, &sm[A2], &sm[C2], t);

        // stage ALL weights once: [ci24][kh][grp][c3*3+kw] (12-float groups)
        for (int idx = t; idx < 2592; idx += 512) {
            int co = idx / 216, rem = idx % 216;
            int ci = rem / 9, kh = (rem % 9) / 3, kw = rem % 3;
            sm[W2 + ((ci * 3 + kh) * 4 + co / 3) * 12 + (co % 3) * 3 + kw] =
                w2[((cg * 12 + co) * 24 + ci) * 9 + kh * 3 + kw];
        }
        __syncthreads();

        const int px = t & 127;
        const int r = px >> 4, wo = px & 15;
        const int grp = t >> 7;
        float acc0 = 0.f, acc1 = 0.f, acc2 = 0.f;

#pragma unroll 1
        for (int ph = 0; ph < 2; ph++) {
            const int cc = ph * 12;
            // stage y1 rows 16*half-1..+15 (17) for 12 ci, BN+ReLU, de-interleaved
            for (int idx = t; idx < 12 * 17 * 32; idx += 512) {
                int ci  = idx / 544;
                int rem = idx - ci * 544;
                int row = rem >> 5, col = rem & 31;
                int hg  = 16 * half - 1 + row;
                float f = 0.f;
                if (hg >= 0) {
                    float y = g_y1[((n * 24 + cc + ci) * 32 + hg) * 32 + col];
                    f = fmaxf(fmaf(sm[A2 + cc + ci], y, sm[C2 + cc + ci]), 0.f);
                }
                if (col & 1) sm[OD2 + ci * 289 + row * 17 + (col >> 1) + 1] = f;
                else         sm[EV2 + ci * 272 + row * 16 + (col >> 1)] = f;
            }
            if (t < 204) sm[OD2 + (t / 17) * 289 + (t % 17) * 17] = 0.f;
            __syncthreads();

#pragma unroll 1
            for (int cil = 0; cil < 12; cil++) {
                const int ci = cc + cil;
#pragma unroll
                for (int kh = 0; kh < 3; kh++) {
                    const int rl = 2 * r + kh;
                    float v0 = sm[OD2 + cil * 289 + rl * 17 + wo];
                    float v1 = sm[EV2 + cil * 272 + rl * 16 + wo];
                    float v2 = sm[OD2 + cil * 289 + rl * 17 + wo + 1];
                    const float* wb = &sm[W2 + ((ci * 3 + kh) * 4 + grp) * 12];
                    float4 wa = *reinterpret_cast<const float4*>(wb);
                    float4 wc = *reinterpret_cast<const float4*>(wb + 4);
                    float w8 = wb[8];
                    acc0 += v0 * wa.x + v1 * wa.y + v2 * wa.z;
                    acc1 += v0 * wa.w + v1 * wc.x + v2 * wc.y;
                    acc2 += v0 * wc.z + v1 * wc.w + v2 * w8;
                }
            }
            __syncthreads();   // before re-staging (and harmless at end)
        }

        const int ho = half * 8 + r;
        const int cb = cg * 12 + grp * 3;
        g_y2[((n * 24 + cb + 0) * 16 + ho) * 16 + wo] = acc0;
        g_y2[((n * 24 + cb + 1) * 16 + ho) * 16 + wo] = acc1;
        g_y2[((n * 24 + cb + 2) * 16 + ho) * 16 + wo] = acc2;

        float av[3] = {acc0, acc1, acc2};
#pragma unroll
        for (int c3 = 0; c3 < 3; c3++) {
            float rs = warp_sum(av[c3]);
            float rq = warp_sum(av[c3] * av[c3]);
            if (lane == 0) {
                int ch = grp * 3 + c3, wg = warp & 3;
                sm[RD2 + ch * 8 + wg * 2] = rs;
                sm[RD2 + ch * 8 + wg * 2 + 1] = rq;
            }
        }
        __syncthreads();
        if (t < 12) {
            float s = 0.f, q = 0.f;
#pragma unroll
            for (int w = 0; w < 4; w++) { s += sm[RD2 + t * 8 + w * 2]; q += sm[RD2 + t * 8 + w * 2 + 1]; }
            g_p2s[(cg * 12 + t) * 64 + n * 2 + half] = s;
            g_p2q[(cg * 12 + t) * 64 + n * 2 + half] = q;
        }
    }

    grid_barrier();

    // ============================ PHASE 3: head ============================
    // 128 blocks = 32n x 4 chunks (256 fc1 outputs each).
    {
        const int n = bid >> 2;
        const int chunk = bid & 3;

        compute_bn24(g_p2s, g_p2q, 1.f / 8192.f, bn2_g, bn2_b, &sm[HA], &sm[HC], t);
        if (t >= 384) sm[HQ + t - 384] = ques[n * 128 + t - 384];
        __syncthreads();

        // spatial sums of relu(bn2(y2)); coord sums are exactly 0
        if (t < 384) {
            int c = t >> 4, g = t & 15;
            const float* yp = &g_y2[(n * 24 + c) * 256 + g * 16];
            float a = sm[HA + c], cc = sm[HC + c];
            float acc = 0.f;
#pragma unroll
            for (int i = 0; i < 16; i++) acc += fmaxf(fmaf(a, yp[i], cc), 0.f);
            sm[HP + c * 16 + g] = acc;
        }
        __syncthreads();
        if (t < 26) {
            float s = 0.f;
            if (t < 24) {
#pragma unroll
                for (int g = 0; g < 16; g++) s += sm[HP + t * 16 + g];
            }
            sm[HS + t] = s;
        }
        __syncthreads();

        // relations: j = t&127, k-quarter kk = t>>7
        {
            const int j = t & 127, kk = t >> 7;
            float r2 = (kk == 0) ? b_rel[j] : 0.f;
            const float* wq = &w_rel[(52 + kk * 32) * 128 + j];
#pragma unroll 8
            for (int q = 0; q < 32; q++)
                r2 = fmaf(sm[HQ + kk * 32 + q], wq[q * 128], r2);
            sm[HRB + kk * 128 + j] = r2;
            if (kk == 0) {
                float r1 = 0.f;
#pragma unroll
                for (int k = 0; k < 26; k++)
                    r1 += sm[HS + k] * (w_rel[k * 128 + j] + w_rel[(26 + k) * 128 + j]);
                sm[HRA + j] = r1;
            }
        }
        __syncthreads();
        if (t < 128)
            sm[HR + t] = 256.f * sm[HRA + t] +
                         65536.f * (sm[HRB + t] + sm[HRB + 128 + t] +
                                    sm[HRB + 256 + t] + sm[HRB + 384 + t]);
        __syncthreads();

        // fc1: 256 outputs, k split in halves (kh2 = t>>8)
        {
            const int jj = t & 255, kh2 = t >> 8;
            const int j = chunk * 256 + jj;
            float acc = (kh2 == 0) ? b_fc1[j] : 0.f;
            const float* wp = &w_fc1[(kh2 * 64) * 1024 + j];
            const float* rp = &sm[HR + kh2 * 64];
#pragma unroll 8
            for (int k = 0; k < 64; k++)
                acc = fmaf(rp[k], wp[k * 1024], acc);
            sm[HH + t] = acc;
        }
        __syncthreads();
        // relu + partial fc2
        {
            float p0 = 0.f, p1 = 0.f;
            if (t < 256) {
                float hv = fmaxf(sm[HH + t] + sm[HH + t + 256], 0.f);
                const int j = chunk * 256 + t;
                p0 = hv * w_fc2[j * 2];
                p1 = hv * w_fc2[j * 2 + 1];
            }
            p0 = warp_sum(p0);
            p1 = warp_sum(p1);
            if (lane == 0 && warp < 8) { sm[HO + warp * 2] = p0; sm[HO + warp * 2 + 1] = p1; }
        }
        __syncthreads();
        if (t == 0) {
            float o0 = 0.f, o1 = 0.f;
#pragma unroll
            for (int w = 0; w < 8; w++) { o0 += sm[HO + w * 2]; o1 += sm[HO + w * 2 + 1]; }
            g_hpart[(n * 4 + chunk) * 2 + 0] = o0;
            g_hpart[(n * 4 + chunk) * 2 + 1] = o1;
            __threadfence();
            unsigned r = atomicAdd(&g_done[n], 1u);
            if (r == 3) {
                __threadfence();
                float f0 = b_fc2[0], f1 = b_fc2[1];
#pragma unroll
                for (int c = 0; c < 4; c++) {
                    f0 += g_hpart[(n * 4 + c) * 2 + 0];
                    f1 += g_hpart[(n * 4 + c) * 2 + 1];
                }
                out[n * 2 + 0] = f0;
                out[n * 2 + 1] = f1;
                g_done[n] = 0;
            }
        }
    }
}

// ---------------- launch ----------------
extern "C" void kernel_launch(void* const* d_in, const int* in_sizes, int n_in,
                              void* d_out, int out_size) {
    (void)in_sizes; (void)n_in; (void)out_size;
    const float* image   = (const float*)d_in[0];
    const float* ques    = (const float*)d_in[1];
    const float* conv1_w = (const float*)d_in[2];
    const float* bn1_g   = (const float*)d_in[4];
    const float* bn1_b   = (const float*)d_in[5];
    const float* conv2_w = (const float*)d_in[6];
    const float* bn2_g   = (const float*)d_in[8];
    const float* bn2_b   = (const float*)d_in[9];
    const float* w_rel   = (const float*)d_in[10];
    const float* b_rel   = (const float*)d_in[11];
    const float* w_fc1   = (const float*)d_in[12];
    const float* b_fc1   = (const float*)d_in[13];
    const float* w_fc2   = (const float*)d_in[14];
    const float* b_fc2   = (const float*)d_in[15];
    float* out = (float*)d_out;

    fused_kernel<<<NB, 512>>>(image, conv1_w, bn1_g, bn1_b,
                              conv2_w, bn2_g, bn2_b,
                              ques, w_rel, b_rel,
                              w_fc1, b_fc1, w_fc2, b_fc2, out);
}

// round 9
// speedup vs baseline: 1.2811x; 1.0077x over previous
#include <cuda_runtime.h>

// ---------------- scratch ----------------
__device__ float g_y1[32 * 24 * 32 * 32];
__device__ float g_y2[32 * 24 * 16 * 16];
__device__ float g_p1s[24 * 64];          // key n*2+h16
__device__ float g_p1q[24 * 64];
__device__ float g_p2s[24 * 64];          // key n*2+half
__device__ float g_p2q[24 * 64];
__device__ float g_hpart[32 * 4 * 2];
__device__ unsigned g_done[32];           // zero-init, self-reset
__device__ unsigned g_cnt1[8 * 32];       // padded group counters
__device__ unsigned g_cnt2;
__device__ volatile unsigned g_bar_gen;

#define NB 128

__device__ __forceinline__ float warp_sum(float v) {
#pragma unroll
    for (int o = 16; o > 0; o >>= 1) v += __shfl_down_sync(0xffffffffu, v, o);
    return v;
}

// Two-level grid barrier: 8 groups x 16, then 8 -> root. 128 blocks, 1/SM.
__device__ __forceinline__ void grid_barrier() {
    __syncthreads();
    if (threadIdx.x == 0) {
        __threadfence();
        unsigned gen = g_bar_gen;
        unsigned r = atomicAdd(&g_cnt1[(blockIdx.x >> 4) * 32], 1u);
        if (r == 15) {
            unsigned r2 = atomicAdd(&g_cnt2, 1u);
            if (r2 == 7) {
                g_cnt2 = 0;
#pragma unroll
                for (int i = 0; i < 8; i++) g_cnt1[i * 32] = 0;
                __threadfence();
                g_bar_gen = gen + 1;
            } else {
                while (g_bar_gen == gen) {}
            }
        } else {
            while (g_bar_gen == gen) {}
        }
        __threadfence();
    }
    __syncthreads();
}

__device__ __forceinline__ void compute_bn24(const float* __restrict__ ps,
                                             const float* __restrict__ pq,
                                             float invM,
                                             const float* __restrict__ gamma,
                                             const float* __restrict__ beta,
                                             float* s_a, float* s_c, int t) {
    if (t < 192) {
        int c = t >> 3, g = t & 7;
        float s = 0.f, q = 0.f;
        for (int i = g; i < 64; i += 8) { s += ps[c * 64 + i]; q += pq[c * 64 + i]; }
#pragma unroll
        for (int o = 4; o > 0; o >>= 1) {
            s += __shfl_down_sync(0xffffffffu, s, o, 8);
            q += __shfl_down_sync(0xffffffffu, q, o, 8);
        }
        if (g == 0) {
            float mean = s * invM;
            float var  = q * invM - mean * mean;
            float a    = gamma[c] * rsqrtf(var + 1e-5f);
            s_a[c] = a;
            s_c[c] = beta[c] - mean * a;
        }
    }
}

// smem offsets (floats)
#define EV1 0            // [3][33][32]  3168
#define OD1 3168         // [3][33][33]  3267  (col0 = zero pad)
#define W1  6448         // [(ci*3+kh)*3+kw][12] 324
#define RD1 6784         // [12][16][2]  384
#define EV2 0            // [12][17][16] 3264
#define OD2 3264         // [12][17][17] 3468  (col0 pad)
#define W2  6736         // [((ci*3+kh)*4+grp)][12] 3456
#define A2  10192
#define C2  10216
#define RD2 10240        // [12][4][2]   96
// head
#define HQ   0
#define HA   128
#define HC   152
#define HP   176         // 24*16 = 384
#define HS   560         // 26 -> pad 32
#define HRA  592         // 128
#define HRB  720         // 512
#define HR   1232        // 128
#define HH   1360        // 512
#define HO   1872        // 16

__global__ void __launch_bounds__(512, 1) fused_kernel(
    const float* __restrict__ image, const float* __restrict__ w1,
    const float* __restrict__ bn1_g, const float* __restrict__ bn1_b,
    const float* __restrict__ w2, const float* __restrict__ bn2_g,
    const float* __restrict__ bn2_b, const float* __restrict__ ques,
    const float* __restrict__ w_rel, const float* __restrict__ b_rel,
    const float* __restrict__ w_fc1, const float* __restrict__ b_fc1,
    const float* __restrict__ w_fc2, const float* __restrict__ b_fc2,
    float* __restrict__ out) {

    __shared__ __align__(16) float sm[10368];
    const int bid = blockIdx.x;
    const int t = threadIdx.x;
    const int warp = t >> 5, lane = t & 31;

    // ============================ PHASE 1: conv1 ============================
    // 128 blocks = 32n x 2 h16 x 2 cg(12co). 512 thr = 16 out rows x 32 cols.
    {
        const int n = bid >> 2;
        const int h16 = (bid >> 1) & 1;
        const int cg = bid & 1;

        // stage input rows 32*h16-1 .. +31 (33), de-interleaved even/odd cols
        for (int idx = t; idx < 3 * 33 * 64; idx += 512) {
            int ci  = idx / 2112;
            int rem = idx - ci * 2112;
            int row = rem >> 6, col = rem & 63;
            int hg  = 32 * h16 - 1 + row;
            float v = (hg >= 0) ? image[((n * 3 + ci) * 64 + hg) * 64 + col] : 0.f;
            if (col & 1) sm[OD1 + ci * 1089 + row * 33 + (col >> 1) + 1] = v;
            else         sm[EV1 + ci * 1056 + row * 32 + (col >> 1)] = v;
        }
        if (t < 99) sm[OD1 + (t / 33) * 1089 + (t % 33) * 33] = 0.f;
        // weights -> [ci][kh][kw][co]
        if (t < 324) {
            int co = t / 27, rem = t % 27;
            int ci = rem / 9, kh = (rem % 9) / 3, kw = rem % 3;
            sm[W1 + ((ci * 3 + kh) * 3 + kw) * 12 + co] = w1[(cg * 12 + co) * 27 + rem];
        }
        __syncthreads();

        const int r = t >> 5, wo = t & 31;   // 1 px/thread
        float acc[12];
#pragma unroll
        for (int co = 0; co < 12; co++) acc[co] = 0.f;

#pragma unroll 1
        for (int ci = 0; ci < 3; ci++) {
#pragma unroll
            for (int kh = 0; kh < 3; kh++) {
                const int rl = 2 * r + kh;
                float vv[3];
                vv[0] = sm[OD1 + ci * 1089 + rl * 33 + wo];       // col 2wo-1
                vv[1] = sm[EV1 + ci * 1056 + rl * 32 + wo];       // col 2wo
                vv[2] = sm[OD1 + ci * 1089 + rl * 33 + wo + 1];   // col 2wo+1
                const float4* wp = reinterpret_cast<const float4*>(&sm[W1 + (ci * 3 + kh) * 36]);
#pragma unroll
                for (int kw = 0; kw < 3; kw++) {
                    float v = vv[kw];
                    float4 a = wp[kw * 3], b = wp[kw * 3 + 1], c = wp[kw * 3 + 2];
                    acc[0] += v * a.x;  acc[1] += v * a.y;  acc[2]  += v * a.z;  acc[3]  += v * a.w;
                    acc[4] += v * b.x;  acc[5] += v * b.y;  acc[6]  += v * b.z;  acc[7]  += v * b.w;
                    acc[8] += v * c.x;  acc[9] += v * c.y;  acc[10] += v * c.z;  acc[11] += v * c.w;
                }
            }
        }

#pragma unroll
        for (int co = 0; co < 12; co++)
            g_y1[((n * 24 + cg * 12 + co) * 32 + h16 * 16 + r) * 32 + wo] = acc[co];

#pragma unroll
        for (int co = 0; co < 12; co++) {
            float rs = warp_sum(acc[co]);
            float rq = warp_sum(acc[co] * acc[co]);
            if (lane == 0) { sm[RD1 + co * 32 + warp * 2] = rs; sm[RD1 + co * 32 + warp * 2 + 1] = rq; }
        }
        __syncthreads();
        if (t < 12) {
            float s = 0.f, q = 0.f;
#pragma unroll
            for (int w = 0; w < 16; w++) { s += sm[RD1 + t * 32 + w * 2]; q += sm[RD1 + t * 32 + w * 2 + 1]; }
            g_p1s[(cg * 12 + t) * 64 + n * 2 + h16] = s;
            g_p1q[(cg * 12 + t) * 64 + n * 2 + h16] = q;
        }
    }

    grid_barrier();

    // ============================ PHASE 2: conv2 ============================
    // 128 blocks = 32n x 2 half(8 rows) x 2 cg(12co).
    // 512 thr: px = t&127 (8x16), grp = t>>7 (0..3) -> 3 co each.
    {
        const int n = bid >> 2;
        const int half = (bid >> 1) & 1;
        const int cg = bid & 1;

        compute_bn24(g_p1s, g_p1q, 1.f / 32768.f, bn1_g, bn1_b, &sm[A2], &sm[C2], t);

        // stage ALL weights once: [ci24][kh][grp][c3*3+kw] (12-float groups)
        for (int idx = t; idx < 2592; idx += 512) {
            int co = idx / 216, rem = idx % 216;
            int ci = rem / 9, kh = (rem % 9) / 3, kw = rem % 3;
            sm[W2 + ((ci * 3 + kh) * 4 + co / 3) * 12 + (co % 3) * 3 + kw] =
                w2[((cg * 12 + co) * 24 + ci) * 9 + kh * 3 + kw];
        }
        __syncthreads();

        const int px = t & 127;
        const int r = px >> 4, wo = px & 15;
        const int grp = t >> 7;
        float acc0 = 0.f, acc1 = 0.f, acc2 = 0.f;

#pragma unroll 1
        for (int ph = 0; ph < 2; ph++) {
            const int cc = ph * 12;
            // stage y1 rows 16*half-1..+15 (17) for 12 ci, BN+ReLU, de-interleaved
            for (int idx = t; idx < 12 * 17 * 32; idx += 512) {
                int ci  = idx / 544;
                int rem = idx - ci * 544;
                int row = rem >> 5, col = rem & 31;
                int hg  = 16 * half - 1 + row;
                float f = 0.f;
                if (hg >= 0) {
                    float y = g_y1[((n * 24 + cc + ci) * 32 + hg) * 32 + col];
                    f = fmaxf(fmaf(sm[A2 + cc + ci], y, sm[C2 + cc + ci]), 0.f);
                }
                if (col & 1) sm[OD2 + ci * 289 + row * 17 + (col >> 1) + 1] = f;
                else         sm[EV2 + ci * 272 + row * 16 + (col >> 1)] = f;
            }
            if (t < 204) sm[OD2 + (t / 17) * 289 + (t % 17) * 17] = 0.f;
            __syncthreads();

#pragma unroll 1
            for (int cil = 0; cil < 12; cil++) {
                const int ci = cc + cil;
#pragma unroll
                for (int kh = 0; kh < 3; kh++) {
                    const int rl = 2 * r + kh;
                    float v0 = sm[OD2 + cil * 289 + rl * 17 + wo];
                    float v1 = sm[EV2 + cil * 272 + rl * 16 + wo];
                    float v2 = sm[OD2 + cil * 289 + rl * 17 + wo + 1];
                    const float* wb = &sm[W2 + ((ci * 3 + kh) * 4 + grp) * 12];
                    float4 wa = *reinterpret_cast<const float4*>(wb);
                    float4 wc = *reinterpret_cast<const float4*>(wb + 4);
                    float w8 = wb[8];
                    acc0 += v0 * wa.x + v1 * wa.y + v2 * wa.z;
                    acc1 += v0 * wa.w + v1 * wc.x + v2 * wc.y;
                    acc2 += v0 * wc.z + v1 * wc.w + v2 * w8;
                }
            }
            __syncthreads();   // before re-staging (and harmless at end)
        }

        const int ho = half * 8 + r;
        const int cb = cg * 12 + grp * 3;
        g_y2[((n * 24 + cb + 0) * 16 + ho) * 16 + wo] = acc0;
        g_y2[((n * 24 + cb + 1) * 16 + ho) * 16 + wo] = acc1;
        g_y2[((n * 24 + cb + 2) * 16 + ho) * 16 + wo] = acc2;

        float av[3] = {acc0, acc1, acc2};
#pragma unroll
        for (int c3 = 0; c3 < 3; c3++) {
            float rs = warp_sum(av[c3]);
            float rq = warp_sum(av[c3] * av[c3]);
            if (lane == 0) {
                int ch = grp * 3 + c3, wg = warp & 3;
                sm[RD2 + ch * 8 + wg * 2] = rs;
                sm[RD2 + ch * 8 + wg * 2 + 1] = rq;
            }
        }
        __syncthreads();
        if (t < 12) {
            float s = 0.f, q = 0.f;
#pragma unroll
            for (int w = 0; w < 4; w++) { s += sm[RD2 + t * 8 + w * 2]; q += sm[RD2 + t * 8 + w * 2 + 1]; }
            g_p2s[(cg * 12 + t) * 64 + n * 2 + half] = s;
            g_p2q[(cg * 12 + t) * 64 + n * 2 + half] = q;
        }
    }

    grid_barrier();

    // ============================ PHASE 3: head ============================
    // 128 blocks = 32n x 4 chunks (256 fc1 outputs each).
    {
        const int n = bid >> 2;
        const int chunk = bid & 3;

        compute_bn24(g_p2s, g_p2q, 1.f / 8192.f, bn2_g, bn2_b, &sm[HA], &sm[HC], t);
        if (t >= 384) sm[HQ + t - 384] = ques[n * 128 + t - 384];
        __syncthreads();

        // spatial sums of relu(bn2(y2)); coord sums are exactly 0
        if (t < 384) {
            int c = t >> 4, g = t & 15;
            const float* yp = &g_y2[(n * 24 + c) * 256 + g * 16];
            float a = sm[HA + c], cc = sm[HC + c];
            float acc = 0.f;
#pragma unroll
            for (int i = 0; i < 16; i++) acc += fmaxf(fmaf(a, yp[i], cc), 0.f);
            sm[HP + c * 16 + g] = acc;
        }
        __syncthreads();
        if (t < 26) {
            float s = 0.f;
            if (t < 24) {
#pragma unroll
                for (int g = 0; g < 16; g++) s += sm[HP + t * 16 + g];
            }
            sm[HS + t] = s;
        }
        __syncthreads();

        // relations: j = t&127, k-quarter kk = t>>7
        {
            const int j = t & 127, kk = t >> 7;
            float r2 = (kk == 0) ? b_rel[j] : 0.f;
            const float* wq = &w_rel[(52 + kk * 32) * 128 + j];
#pragma unroll 8
            for (int q = 0; q < 32; q++)
                r2 = fmaf(sm[HQ + kk * 32 + q], wq[q * 128], r2);
            sm[HRB + kk * 128 + j] = r2;
            if (kk == 0) {
                float r1 = 0.f;
#pragma unroll
                for (int k = 0; k < 26; k++)
                    r1 += sm[HS + k] * (w_rel[k * 128 + j] + w_rel[(26 + k) * 128 + j]);
                sm[HRA + j] = r1;
            }
        }
        __syncthreads();
        if (t < 128)
            sm[HR + t] = 256.f * sm[HRA + t] +
                         65536.f * (sm[HRB + t] + sm[HRB + 128 + t] +
                                    sm[HRB + 256 + t] + sm[HRB + 384 + t]);
        __syncthreads();

        // fc1: 256 outputs, k split in halves (kh2 = t>>8)
        {
            const int jj = t & 255, kh2 = t >> 8;
            const int j = chunk * 256 + jj;
            float acc = (kh2 == 0) ? b_fc1[j] : 0.f;
            const float* wp = &w_fc1[(kh2 * 64) * 1024 + j];
            const float* rp = &sm[HR + kh2 * 64];
#pragma unroll 8
            for (int k = 0; k < 64; k++)
                acc = fmaf(rp[k], wp[k * 1024], acc);
            sm[HH + t] = acc;
        }
        __syncthreads();
        // relu + partial fc2
        {
            float p0 = 0.f, p1 = 0.f;
            if (t < 256) {
                float hv = fmaxf(sm[HH + t] + sm[HH + t + 256], 0.f);
                const int j = chunk * 256 + t;
                p0 = hv * w_fc2[j * 2];
                p1 = hv * w_fc2[j * 2 + 1];
            }
            p0 = warp_sum(p0);
            p1 = warp_sum(p1);
            if (lane == 0 && warp < 8) { sm[HO + warp * 2] = p0; sm[HO + warp * 2 + 1] = p1; }
        }
        __syncthreads();
        if (t == 0) {
            float o0 = 0.f, o1 = 0.f;
#pragma unroll
            for (int w = 0; w < 8; w++) { o0 += sm[HO + w * 2]; o1 += sm[HO + w * 2 + 1]; }
            g_hpart[(n * 4 + chunk) * 2 + 0] = o0;
            g_hpart[(n * 4 + chunk) * 2 + 1] = o1;
            __threadfence();
            unsigned r = atomicAdd(&g_done[n], 1u);
            if (r == 3) {
                __threadfence();
                float f0 = b_fc2[0], f1 = b_fc2[1];
#pragma unroll
                for (int c = 0; c < 4; c++) {
                    f0 += g_hpart[(n * 4 + c) * 2 + 0];
                    f1 += g_hpart[(n * 4 + c) * 2 + 1];
                }
                out[n * 2 + 0] = f0;
                out[n * 2 + 1] = f1;
                g_done[n] = 0;
            }
        }
    }
}

// ---------------- launch ----------------
extern "C" void kernel_launch(void* const* d_in, const int* in_sizes, int n_in,
                              void* d_out, int out_size) {
    (void)in_sizes; (void)n_in; (void)out_size;
    const float* image   = (const float*)d_in[0];
    const float* ques    = (const float*)d_in[1];
    const float* conv1_w = (const float*)d_in[2];
    const float* bn1_g   = (const float*)d_in[4];
    const float* bn1_b   = (const float*)d_in[5];
    const float* conv2_w = (const float*)d_in[6];
    const float* bn2_g   = (const float*)d_in[8];
    const float* bn2_b   = (const float*)d_in[9];
    const float* w_rel   = (const float*)d_in[10];
    const float* b_rel   = (const float*)d_in[11];
    const float* w_fc1   = (const float*)d_in[12];
    const float* b_fc1   = (const float*)d_in[13];
    const float* w_fc2   = (const float*)d_in[14];
    const float* b_fc2   = (const float*)d_in[15];
    float* out = (float*)d_out;

    fused_kernel<<<NB, 512>>>(image, conv1_w, bn1_g, bn1_b,
                              conv2_w, bn2_g, bn2_b,
                              ques, w_rel, b_rel,
                              w_fc1, b_fc1, w_fc2, b_fc2, out);
}

// round 10
// speedup vs baseline: 1.3456x; 1.0504x over previous
#include <cuda_runtime.h>

// ---------------- scratch ----------------
// y1 de-interleaved: [n][ci24][33 rows][36]; stored row = y1row+1;
// offset j in [0,16): col 2j ("ev"); offset 16+j, j in [0,17): col 2j-1 ("od", j=0 pad)
__device__ float g_y1[32 * 24 * 33 * 36];
__device__ float g_y2[32 * 24 * 16 * 16];
__device__ float g_p1s[24 * 64];          // key n*2+h16
__device__ float g_p1q[24 * 64];
__device__ float g_p2s[24 * 64];          // key n*2+half
__device__ float g_p2q[24 * 64];
__device__ float g_hpart[32 * 4 * 2];
__device__ unsigned g_done[32];           // zero-init, self-reset
__device__ unsigned g_cnt1[8 * 32];       // padded group counters
__device__ unsigned g_cnt2;
__device__ volatile unsigned g_bar_gen;

#define NB 128

__device__ __forceinline__ float warp_sum(float v) {
#pragma unroll
    for (int o = 16; o > 0; o >>= 1) v += __shfl_down_sync(0xffffffffu, v, o);
    return v;
}

// Two-level grid barrier: 8 groups x 16, then 8 -> root. 128 blocks, 1/SM.
__device__ __forceinline__ void grid_barrier() {
    __syncthreads();
    if (threadIdx.x == 0) {
        __threadfence();
        unsigned gen = g_bar_gen;
        unsigned r = atomicAdd(&g_cnt1[(blockIdx.x >> 4) * 32], 1u);
        if (r == 15) {
            unsigned r2 = atomicAdd(&g_cnt2, 1u);
            if (r2 == 7) {
                g_cnt2 = 0;
#pragma unroll
                for (int i = 0; i < 8; i++) g_cnt1[i * 32] = 0;
                __threadfence();
                g_bar_gen = gen + 1;
            } else {
                while (g_bar_gen == gen) {}
            }
        } else {
            while (g_bar_gen == gen) {}
        }
        __threadfence();
    }
    __syncthreads();
}

__device__ __forceinline__ void compute_bn24(const float* __restrict__ ps,
                                             const float* __restrict__ pq,
                                             float invM,
                                             const float* __restrict__ gamma,
                                             const float* __restrict__ beta,
                                             float* s_a, float* s_c, int t) {
    if (t < 192) {
        int c = t >> 3, g = t & 7;
        float s = 0.f, q = 0.f;
        for (int i = g; i < 64; i += 8) { s += ps[c * 64 + i]; q += pq[c * 64 + i]; }
#pragma unroll
        for (int o = 4; o > 0; o >>= 1) {
            s += __shfl_down_sync(0xffffffffu, s, o, 8);
            q += __shfl_down_sync(0xffffffffu, q, o, 8);
        }
        if (g == 0) {
            float mean = s * invM;
            float var  = q * invM - mean * mean;
            float a    = gamma[c] * rsqrtf(var + 1e-5f);
            s_a[c] = a;
            s_c[c] = beta[c] - mean * a;
        }
    }
}

// smem offsets (floats)
// conv1
#define EV1 0            // [3][33][32]  3168
#define OD1 3168         // [3][33][33]  3267 (col0 pad)
#define W1  6448         // [(ci*3+kh)*3+kw][12] 324
#define RD1 6784         // [12][16][2]  384
// conv2
#define T2  0            // [12][17][36] 7344
#define W2  7344         // [((ci*3+kh)*4+grp)][12] 3456
#define A2  10800
#define C2  10824
#define RD2 10848        // [12][4][2] 96
// head
#define HQ   0
#define HA   128
#define HC   152
#define HP   176         // 24*16 = 384
#define HS   560         // pad 32
#define HRA  592         // 128
#define HRB  720         // 512
#define HR   1232        // 128
#define HH   1360        // 512
#define HO   1872        // 16

__global__ void __launch_bounds__(512, 1) fused_kernel(
    const float* __restrict__ image, const float* __restrict__ w1,
    const float* __restrict__ bn1_g, const float* __restrict__ bn1_b,
    const float* __restrict__ w2, const float* __restrict__ bn2_g,
    const float* __restrict__ bn2_b, const float* __restrict__ ques,
    const float* __restrict__ w_rel, const float* __restrict__ b_rel,
    const float* __restrict__ w_fc1, const float* __restrict__ b_fc1,
    const float* __restrict__ w_fc2, const float* __restrict__ b_fc2,
    float* __restrict__ out) {

    __shared__ __align__(16) float sm[10944];
    const int bid = blockIdx.x;
    const int t = threadIdx.x;
    const int warp = t >> 5, lane = t & 31;

    // ============================ PHASE 1: conv1 ============================
    // 128 blocks = 32n x 2 h16 x 2 cg(12co). 512 thr = 16 out rows x 32 cols.
    {
        const int n = bid >> 2;
        const int h16 = (bid >> 1) & 1;
        const int cg = bid & 1;

        // stage input rows 32*h16-1 .. +31 via float4 (3*33*16 = 1584 quads)
#pragma unroll
        for (int i = 0; i < 4; i++) {
            int idx = t + i * 512;
            if (idx < 1584) {
                int ci  = idx / 528;
                int rem = idx - ci * 528;
                int row = rem >> 4, c4 = rem & 15;
                int hg  = 32 * h16 - 1 + row;
                float4 v = make_float4(0.f, 0.f, 0.f, 0.f);
                if (hg >= 0)
                    v = *reinterpret_cast<const float4*>(
                        &image[((n * 3 + ci) * 64 + hg) * 64 + c4 * 4]);
                // cols 4c..4c+3 -> ev[2c]=x, od[2c+1]=y, ev[2c+1]=z, od[2c+2]=w
                *reinterpret_cast<float2*>(&sm[EV1 + ci * 1056 + row * 32 + 2 * c4]) =
                    make_float2(v.x, v.z);
                sm[OD1 + ci * 1089 + row * 33 + 2 * c4 + 1] = v.y;
                sm[OD1 + ci * 1089 + row * 33 + 2 * c4 + 2] = v.w;
            }
        }
        if (t < 99) sm[OD1 + (t / 33) * 1089 + (t % 33) * 33] = 0.f;
        if (t < 324) {
            int co = t / 27, rem = t % 27;
            int ci = rem / 9, kh = (rem % 9) / 3, kw = rem % 3;
            sm[W1 + ((ci * 3 + kh) * 3 + kw) * 12 + co] = w1[(cg * 12 + co) * 27 + rem];
        }
        __syncthreads();

        const int r = t >> 5, wo = t & 31;   // 1 px/thread
        float acc[12];
#pragma unroll
        for (int co = 0; co < 12; co++) acc[co] = 0.f;

#pragma unroll 1
        for (int ci = 0; ci < 3; ci++) {
#pragma unroll
            for (int kh = 0; kh < 3; kh++) {
                const int rl = 2 * r + kh;
                float vv[3];
                vv[0] = sm[OD1 + ci * 1089 + rl * 33 + wo];       // col 2wo-1
                vv[1] = sm[EV1 + ci * 1056 + rl * 32 + wo];       // col 2wo
                vv[2] = sm[OD1 + ci * 1089 + rl * 33 + wo + 1];   // col 2wo+1
                const float4* wp = reinterpret_cast<const float4*>(&sm[W1 + (ci * 3 + kh) * 36]);
#pragma unroll
                for (int kw = 0; kw < 3; kw++) {
                    float v = vv[kw];
                    float4 a = wp[kw * 3], b = wp[kw * 3 + 1], c = wp[kw * 3 + 2];
                    acc[0] += v * a.x;  acc[1] += v * a.y;  acc[2]  += v * a.z;  acc[3]  += v * a.w;
                    acc[4] += v * b.x;  acc[5] += v * b.y;  acc[6]  += v * b.z;  acc[7]  += v * b.w;
                    acc[8] += v * c.x;  acc[9] += v * c.y;  acc[10] += v * c.z;  acc[11] += v * c.w;
                }
            }
        }

        // store y1 de-interleaved: stored row = y1row+1; off per parity of wo
        {
            const int off = (wo & 1) ? (17 + (wo >> 1)) : (wo >> 1);
            const int row_s = 16 * h16 + r + 1;
#pragma unroll
            for (int co = 0; co < 12; co++)
                g_y1[((n * 24 + cg * 12 + co) * 33 + row_s) * 36 + off] = acc[co];
        }

#pragma unroll
        for (int co = 0; co < 12; co++) {
            float rs = warp_sum(acc[co]);
            float rq = warp_sum(acc[co] * acc[co]);
            if (lane == 0) { sm[RD1 + co * 32 + warp * 2] = rs; sm[RD1 + co * 32 + warp * 2 + 1] = rq; }
        }
        __syncthreads();
        if (t < 12) {
            float s = 0.f, q = 0.f;
#pragma unroll
            for (int w = 0; w < 16; w++) { s += sm[RD1 + t * 32 + w * 2]; q += sm[RD1 + t * 32 + w * 2 + 1]; }
            g_p1s[(cg * 12 + t) * 64 + n * 2 + h16] = s;
            g_p1q[(cg * 12 + t) * 64 + n * 2 + h16] = q;
        }
    }

    grid_barrier();

    // ============================ PHASE 2: conv2 ============================
    // 128 blocks = 32n x 2 half(8 rows) x 2 cg(12co).
    // 512 thr: px = t&127 (8x16), grp = t>>7 (0..3) -> 3 co each.
    {
        const int n = bid >> 2;
        const int half = (bid >> 1) & 1;
        const int cg = bid & 1;

        compute_bn24(g_p1s, g_p1q, 1.f / 32768.f, bn1_g, bn1_b, &sm[A2], &sm[C2], t);

        // stage ALL weights once: [ci24][kh][grp][c3*3+kw]
        for (int idx = t; idx < 2592; idx += 512) {
            int co = idx / 216, rem = idx % 216;
            int ci = rem / 9, kh = (rem % 9) / 3, kw = rem % 3;
            sm[W2 + ((ci * 3 + kh) * 4 + co / 3) * 12 + (co % 3) * 3 + kw] =
                w2[((cg * 12 + co) * 24 + ci) * 9 + kh * 3 + kw];
        }
        __syncthreads();

        const int px = t & 127;
        const int r = px >> 4, wo = px & 15;
        const int grp = t >> 7;
        float acc0 = 0.f, acc1 = 0.f, acc2 = 0.f;

#pragma unroll 1
        for (int ph = 0; ph < 2; ph++) {
            const int cc = ph * 12;
            // stage 12 ci x 17 stored rows x 9 float4 = 1836 quads, BN+ReLU fused
#pragma unroll
            for (int i = 0; i < 4; i++) {
                int idx = t + i * 512;
                if (idx < 1836) {
                    int ci  = idx / 153;
                    int rem = idx - ci * 153;
                    int rr  = rem / 9;
                    int f4o = rem - rr * 9;
                    float4 y = *reinterpret_cast<const float4*>(
                        &g_y1[((n * 24 + cc + ci) * 33 + 16 * half + rr) * 36 + f4o * 4]);
                    float a = sm[A2 + cc + ci], c = sm[C2 + cc + ci];
                    float4 f;
                    f.x = fmaxf(fmaf(a, y.x, c), 0.f);
                    f.y = fmaxf(fmaf(a, y.y, c), 0.f);
                    f.z = fmaxf(fmaf(a, y.z, c), 0.f);
                    f.w = fmaxf(fmaf(a, y.w, c), 0.f);
                    if (f4o == 4) f.x = 0.f;                 // od col -1 pad
                    if (half + rr == 0) f = make_float4(0.f, 0.f, 0.f, 0.f);  // y1 row -1
                    *reinterpret_cast<float4*>(&sm[T2 + ci * 612 + rr * 36 + f4o * 4]) = f;
                }
            }
            __syncthreads();

#pragma unroll 1
            for (int cil = 0; cil < 12; cil++) {
                const int ci = cc + cil;
#pragma unroll
                for (int kh = 0; kh < 3; kh++) {
                    const int rl = 2 * r + kh;
                    const float* tb = &sm[T2 + cil * 612 + rl * 36];
                    float v0 = tb[16 + wo];   // col 2wo-1
                    float v1 = tb[wo];        // col 2wo
                    float v2 = tb[17 + wo];   // col 2wo+1
                    const float* wb = &sm[W2 + ((ci * 3 + kh) * 4 + grp) * 12];
                    float4 wa = *reinterpret_cast<const float4*>(wb);
                    float4 wc = *reinterpret_cast<const float4*>(wb + 4);
                    float w8 = wb[8];
                    acc0 += v0 * wa.x + v1 * wa.y + v2 * wa.z;
                    acc1 += v0 * wa.w + v1 * wc.x + v2 * wc.y;
                    acc2 += v0 * wc.z + v1 * wc.w + v2 * w8;
                }
            }
            __syncthreads();   // before re-staging
        }

        const int ho = half * 8 + r;
        const int cb = cg * 12 + grp * 3;
        g_y2[((n * 24 + cb + 0) * 16 + ho) * 16 + wo] = acc0;
        g_y2[((n * 24 + cb + 1) * 16 + ho) * 16 + wo] = acc1;
        g_y2[((n * 24 + cb + 2) * 16 + ho) * 16 + wo] = acc2;

        float av[3] = {acc0, acc1, acc2};
#pragma unroll
        for (int c3 = 0; c3 < 3; c3++) {
            float rs = warp_sum(av[c3]);
            float rq = warp_sum(av[c3] * av[c3]);
            if (lane == 0) {
                int ch = grp * 3 + c3, wg = warp & 3;
                sm[RD2 + ch * 8 + wg * 2] = rs;
                sm[RD2 + ch * 8 + wg * 2 + 1] = rq;
            }
        }
        __syncthreads();
        if (t < 12) {
            float s = 0.f, q = 0.f;
#pragma unroll
            for (int w = 0; w < 4; w++) { s += sm[RD2 + t * 8 + w * 2]; q += sm[RD2 + t * 8 + w * 2 + 1]; }
            g_p2s[(cg * 12 + t) * 64 + n * 2 + half] = s;
            g_p2q[(cg * 12 + t) * 64 + n * 2 + half] = q;
        }
    }

    grid_barrier();

    // ============================ PHASE 3: head ============================
    // 128 blocks = 32n x 4 chunks (256 fc1 outputs each).
    {
        const int n = bid >> 2;
        const int chunk = bid & 3;

        compute_bn24(g_p2s, g_p2q, 1.f / 8192.f, bn2_g, bn2_b, &sm[HA], &sm[HC], t);
        if (t >= 384) sm[HQ + t - 384] = ques[n * 128 + t - 384];
        __syncthreads();

        // spatial sums of relu(bn2(y2)); coord sums are exactly 0
        if (t < 384) {
            int c = t >> 4, g = t & 15;
            const float* yp = &g_y2[(n * 24 + c) * 256 + g * 16];
            float a = sm[HA + c], cc = sm[HC + c];
            float acc = 0.f;
#pragma unroll
            for (int i = 0; i < 16; i++) acc += fmaxf(fmaf(a, yp[i], cc), 0.f);
            sm[HP + c * 16 + g] = acc;
        }
        __syncthreads();
        if (t < 26) {
            float s = 0.f;
            if (t < 24) {
#pragma unroll
                for (int g = 0; g < 16; g++) s += sm[HP + t * 16 + g];
            }
            sm[HS + t] = s;
        }
        __syncthreads();

        // relations: j = t&127, k-quarter kk = t>>7
        {
            const int j = t & 127, kk = t >> 7;
            float r2 = (kk == 0) ? b_rel[j] : 0.f;
            const float* wq = &w_rel[(52 + kk * 32) * 128 + j];
#pragma unroll 8
            for (int q = 0; q < 32; q++)
                r2 = fmaf(sm[HQ + kk * 32 + q], wq[q * 128], r2);
            sm[HRB + kk * 128 + j] = r2;
            if (kk == 0) {
                float r1 = 0.f;
#pragma unroll
                for (int k = 0; k < 26; k++)
                    r1 += sm[HS + k] * (w_rel[k * 128 + j] + w_rel[(26 + k) * 128 + j]);
                sm[HRA + j] = r1;
            }
        }
        __syncthreads();
        if (t < 128)
            sm[HR + t] = 256.f * sm[HRA + t] +
                         65536.f * (sm[HRB + t] + sm[HRB + 128 + t] +
                                    sm[HRB + 256 + t] + sm[HRB + 384 + t]);
        __syncthreads();

        // fc1: 256 outputs, k split in halves (kh2 = t>>8)
        {
            const int jj = t & 255, kh2 = t >> 8;
            const int j = chunk * 256 + jj;
            float acc = (kh2 == 0) ? b_fc1[j] : 0.f;
            const float* wp = &w_fc1[(kh2 * 64) * 1024 + j];
            const float* rp = &sm[HR + kh2 * 64];
#pragma unroll 16
            for (int k = 0; k < 64; k++)
                acc = fmaf(rp[k], wp[k * 1024], acc);
            sm[HH + t] = acc;
        }
        __syncthreads();
        // relu + partial fc2
        {
            float p0 = 0.f, p1 = 0.f;
            if (t < 256) {
                float hv = fmaxf(sm[HH + t] + sm[HH + t + 256], 0.f);
                const int j = chunk * 256 + t;
                p0 = hv * w_fc2[j * 2];
                p1 = hv * w_fc2[j * 2 + 1];
            }
            p0 = warp_sum(p0);
            p1 = warp_sum(p1);
            if (lane == 0 && warp < 8) { sm[HO + warp * 2] = p0; sm[HO + warp * 2 + 1] = p1; }
        }
        __syncthreads();
        if (t == 0) {
            float o0 = 0.f, o1 = 0.f;
#pragma unroll
            for (int w = 0; w < 8; w++) { o0 += sm[HO + w * 2]; o1 += sm[HO + w * 2 + 1]; }
            g_hpart[(n * 4 + chunk) * 2 + 0] = o0;
            g_hpart[(n * 4 + chunk) * 2 + 1] = o1;
            __threadfence();
            unsigned r = atomicAdd(&g_done[n], 1u);
            if (r == 3) {
                __threadfence();
                float f0 = b_fc2[0], f1 = b_fc2[1];
#pragma unroll
                for (int c = 0; c < 4; c++) {
                    f0 += g_hpart[(n * 4 + c) * 2 + 0];
                    f1 += g_hpart[(n * 4 + c) * 2 + 1];
                }
                out[n * 2 + 0] = f0;
                out[n * 2 + 1] = f1;
                g_done[n] = 0;
            }
        }
    }
}

// ---------------- launch ----------------
extern "C" void kernel_launch(void* const* d_in, const int* in_sizes, int n_in,
                              void* d_out, int out_size) {
    (void)in_sizes; (void)n_in; (void)out_size;
    const float* image   = (const float*)d_in[0];
    const float* ques    = (const float*)d_in[1];
    const float* conv1_w = (const float*)d_in[2];
    const float* bn1_g   = (const float*)d_in[4];
    const float* bn1_b   = (const float*)d_in[5];
    const float* conv2_w = (const float*)d_in[6];
    const float* bn2_g   = (const float*)d_in[8];
    const float* bn2_b   = (const float*)d_in[9];
    const float* w_rel   = (const float*)d_in[10];
    const float* b_rel   = (const float*)d_in[11];
    const float* w_fc1   = (const float*)d_in[12];
    const float* b_fc1   = (const float*)d_in[13];
    const float* w_fc2   = (const float*)d_in[14];
    const float* b_fc2   = (const float*)d_in[15];
    float* out = (float*)d_out;

    fused_kernel<<<NB, 512>>>(image, conv1_w, bn1_g, bn1_b,
                              conv2_w, bn2_g, bn2_b,
                              ques, w_rel, b_rel,
                              w_fc1, b_fc1, w_fc2, b_fc2, out);
}

// round 11
// speedup vs baseline: 1.4279x; 1.0611x over previous
#include <cuda_runtime.h>

// ---------------- scratch ----------------
// y1 de-interleaved: [n][ci24][33 rows][36]; stored row = y1row+1;
// offset j in [0,16): col 2j ("ev"); offset 16+j, j in [0,17): col 2j-1 ("od", j=0 pad)
__device__ float g_y1[32 * 24 * 33 * 36];
__device__ float g_y2[32 * 24 * 16 * 16];
__device__ float g_p1s[24 * 64];          // key n*2+h16
__device__ float g_p1q[24 * 64];
__device__ float g_p2s[24 * 64];          // key n*2+half
__device__ float g_p2q[24 * 64];
__device__ float g_hpart[32 * 4 * 2];
__device__ unsigned g_done[32];           // zero-init, self-reset
__device__ unsigned g_cnt1[8 * 32];       // padded group counters
__device__ unsigned g_cnt2;
__device__ volatile unsigned g_bar_gen;

#define NB 128

__device__ __forceinline__ float warp_sum(float v) {
#pragma unroll
    for (int o = 16; o > 0; o >>= 1) v += __shfl_down_sync(0xffffffffu, v, o);
    return v;
}

// Two-level grid barrier: 8 groups x 16, then 8 -> root. 128 blocks, 1/SM.
__device__ __forceinline__ void grid_barrier() {
    __syncthreads();
    if (threadIdx.x == 0) {
        __threadfence();
        unsigned gen = g_bar_gen;
        unsigned r = atomicAdd(&g_cnt1[(blockIdx.x >> 4) * 32], 1u);
        if (r == 15) {
            unsigned r2 = atomicAdd(&g_cnt2, 1u);
            if (r2 == 7) {
                g_cnt2 = 0;
#pragma unroll
                for (int i = 0; i < 8; i++) g_cnt1[i * 32] = 0;
                __threadfence();
                g_bar_gen = gen + 1;
            } else {
                while (g_bar_gen == gen) {}
            }
        } else {
            while (g_bar_gen == gen) {}
        }
        __threadfence();
    }
    __syncthreads();
}

__device__ __forceinline__ void compute_bn24(const float* __restrict__ ps,
                                             const float* __restrict__ pq,
                                             float invM,
                                             const float* __restrict__ gamma,
                                             const float* __restrict__ beta,
                                             float* s_a, float* s_c, int t) {
    if (t < 192) {
        int c = t >> 3, g = t & 7;
        float s = 0.f, q = 0.f;
        for (int i = g; i < 64; i += 8) { s += ps[c * 64 + i]; q += pq[c * 64 + i]; }
#pragma unroll
        for (int o = 4; o > 0; o >>= 1) {
            s += __shfl_down_sync(0xffffffffu, s, o, 8);
            q += __shfl_down_sync(0xffffffffu, q, o, 8);
        }
        if (g == 0) {
            float mean = s * invM;
            float var  = q * invM - mean * mean;
            float a    = gamma[c] * rsqrtf(var + 1e-5f);
            s_a[c] = a;
            s_c[c] = beta[c] - mean * a;
        }
    }
}

// smem offsets (floats)
// conv1
#define EV1 0            // [3][33][32]  3168
#define OD1 3168         // [3][33][33]  3267 (col0 pad)
#define W1  6448         // [(ci*3+kh)*3+kw][12] 324
#define RD1 6784         // [12][16][2]  384
// conv2 (double-buffered chunks of 6 ci)
// per ci: ev[17][20] @0, od[17][20] @340 -> 680; per buffer 6*680 = 4080
#define T2  0            // 2 buffers: 8160
#define W2  8160         // [((ci*3+kh)*4+grp)][12] 3456
#define A2  11616
#define C2  11640
#define RD2 11664        // [12][4][2] 96
// head
#define HQ   0
#define HA   128
#define HC   152
#define HP   176         // 24*16 = 384
#define HS   560         // pad 32
#define HRA  592         // 128
#define HRB  720         // 512
#define HR   1232        // 128
#define HH   1360        // 512
#define HO   1872        // 16

// stage one quad of chunk ck (idx in [0,918)): load from g_y1, BN+ReLU, pad.
__device__ __forceinline__ void stage_one(int n, int half, int ck, int idx,
                                          const float* sA, const float* sC,
                                          float4& out, int& dst) {
    int ci_l = idx / 153;
    int rem  = idx - ci_l * 153;
    int rr   = rem / 9;
    int f4o  = rem - rr * 9;
    int ci   = ck * 6 + ci_l;
    float4 y = *reinterpret_cast<const float4*>(
        &g_y1[((n * 24 + ci) * 33 + 16 * half + rr) * 36 + f4o * 4]);
    float a = sA[ci], c = sC[ci];
    float4 f;
    f.x = fmaxf(fmaf(a, y.x, c), 0.f);
    f.y = fmaxf(fmaf(a, y.y, c), 0.f);
    f.z = fmaxf(fmaf(a, y.z, c), 0.f);
    f.w = fmaxf(fmaf(a, y.w, c), 0.f);
    if (f4o == 4) f.x = 0.f;                              // od col -1 pad
    if (half + rr == 0) f = make_float4(0.f, 0.f, 0.f, 0.f);  // y1 row -1
    out = f;
    dst = ci_l * 680 + ((f4o < 4) ? (rr * 20 + f4o * 4)
                                  : (340 + rr * 20 + (f4o - 4) * 4));
}

__global__ void __launch_bounds__(512, 1) fused_kernel(
    const float* __restrict__ image, const float* __restrict__ w1,
    const float* __restrict__ bn1_g, const float* __restrict__ bn1_b,
    const float* __restrict__ w2, const float* __restrict__ bn2_g,
    const float* __restrict__ bn2_b, const float* __restrict__ ques,
    const float* __restrict__ w_rel, const float* __restrict__ b_rel,
    const float* __restrict__ w_fc1, const float* __restrict__ b_fc1,
    const float* __restrict__ w_fc2, const float* __restrict__ b_fc2,
    float* __restrict__ out) {

    __shared__ __align__(16) float sm[11760];
    const int bid = blockIdx.x;
    const int t = threadIdx.x;
    const int warp = t >> 5, lane = t & 31;

    // ============================ PHASE 1: conv1 ============================
    // 128 blocks = 32n x 2 h16 x 2 cg(12co). 512 thr = 16 out rows x 32 cols.
    {
        const int n = bid >> 2;
        const int h16 = (bid >> 1) & 1;
        const int cg = bid & 1;

        // stage input rows 32*h16-1 .. +31 via float4 (3*33*16 = 1584 quads)
#pragma unroll
        for (int i = 0; i < 4; i++) {
            int idx = t + i * 512;
            if (idx < 1584) {
                int ci  = idx / 528;
                int rem = idx - ci * 528;
                int row = rem >> 4, c4 = rem & 15;
                int hg  = 32 * h16 - 1 + row;
                float4 v = make_float4(0.f, 0.f, 0.f, 0.f);
                if (hg >= 0)
                    v = *reinterpret_cast<const float4*>(
                        &image[((n * 3 + ci) * 64 + hg) * 64 + c4 * 4]);
                *reinterpret_cast<float2*>(&sm[EV1 + ci * 1056 + row * 32 + 2 * c4]) =
                    make_float2(v.x, v.z);
                sm[OD1 + ci * 1089 + row * 33 + 2 * c4 + 1] = v.y;
                sm[OD1 + ci * 1089 + row * 33 + 2 * c4 + 2] = v.w;
            }
        }
        if (t < 99) sm[OD1 + (t / 33) * 1089 + (t % 33) * 33] = 0.f;
        if (t < 324) {
            int co = t / 27, rem = t % 27;
            int ci = rem / 9, kh = (rem % 9) / 3, kw = rem % 3;
            sm[W1 + ((ci * 3 + kh) * 3 + kw) * 12 + co] = w1[(cg * 12 + co) * 27 + rem];
        }
        __syncthreads();

        const int r = t >> 5, wo = t & 31;   // 1 px/thread
        float acc[12];
#pragma unroll
        for (int co = 0; co < 12; co++) acc[co] = 0.f;

#pragma unroll 1
        for (int ci = 0; ci < 3; ci++) {
#pragma unroll
            for (int kh = 0; kh < 3; kh++) {
                const int rl = 2 * r + kh;
                float vv[3];
                vv[0] = sm[OD1 + ci * 1089 + rl * 33 + wo];
                vv[1] = sm[EV1 + ci * 1056 + rl * 32 + wo];
                vv[2] = sm[OD1 + ci * 1089 + rl * 33 + wo + 1];
                const float4* wp = reinterpret_cast<const float4*>(&sm[W1 + (ci * 3 + kh) * 36]);
#pragma unroll
                for (int kw = 0; kw < 3; kw++) {
                    float v = vv[kw];
                    float4 a = wp[kw * 3], b = wp[kw * 3 + 1], c = wp[kw * 3 + 2];
                    acc[0] += v * a.x;  acc[1] += v * a.y;  acc[2]  += v * a.z;  acc[3]  += v * a.w;
                    acc[4] += v * b.x;  acc[5] += v * b.y;  acc[6]  += v * b.z;  acc[7]  += v * b.w;
                    acc[8] += v * c.x;  acc[9] += v * c.y;  acc[10] += v * c.z;  acc[11] += v * c.w;
                }
            }
        }

        {
            const int off = (wo & 1) ? (17 + (wo >> 1)) : (wo >> 1);
            const int row_s = 16 * h16 + r + 1;
#pragma unroll
            for (int co = 0; co < 12; co++)
                g_y1[((n * 24 + cg * 12 + co) * 33 + row_s) * 36 + off] = acc[co];
        }

#pragma unroll
        for (int co = 0; co < 12; co++) {
            float rs = warp_sum(acc[co]);
            float rq = warp_sum(acc[co] * acc[co]);
            if (lane == 0) { sm[RD1 + co * 32 + warp * 2] = rs; sm[RD1 + co * 32 + warp * 2 + 1] = rq; }
        }
        __syncthreads();
        if (t < 12) {
            float s = 0.f, q = 0.f;
#pragma unroll
            for (int w = 0; w < 16; w++) { s += sm[RD1 + t * 32 + w * 2]; q += sm[RD1 + t * 32 + w * 2 + 1]; }
            g_p1s[(cg * 12 + t) * 64 + n * 2 + h16] = s;
            g_p1q[(cg * 12 + t) * 64 + n * 2 + h16] = q;
        }
    }

    grid_barrier();

    // ============================ PHASE 2: conv2 ============================
    // 128 blocks = 32n x 2 half(8 rows) x 2 cg(12co).
    // 512 thr: grp = t>>7 (3 co each); warp-local px: 4 rows x 8 cols.
    {
        const int n = bid >> 2;
        const int half = (bid >> 1) & 1;
        const int cg = bid & 1;

        compute_bn24(g_p1s, g_p1q, 1.f / 32768.f, bn1_g, bn1_b, &sm[A2], &sm[C2], t);

        // stage ALL weights once: [ci24][kh][grp][c3*3+kw]
        for (int idx = t; idx < 2592; idx += 512) {
            int co = idx / 216, rem = idx % 216;
            int ci = rem / 9, kh = (rem % 9) / 3, kw = rem % 3;
            sm[W2 + ((ci * 3 + kh) * 4 + co / 3) * 12 + (co % 3) * 3 + kw] =
                w2[((cg * 12 + co) * 24 + ci) * 9 + kh * 3 + kw];
        }
        __syncthreads();   // BN consts ready (needed by stage_one)

        // conflict-free px mapping: 4 rows x 8 cols per warp
        const int w4 = warp & 3;
        const int grp = t >> 7;
        const int wo = (lane & 7) | ((w4 & 1) << 3);
        const int r  = (lane >> 3) | ((w4 >> 1) << 2);

        // stage chunk 0 directly
        {
            float4 v; int d;
            stage_one(n, half, 0, t, &sm[A2], &sm[C2], v, d);
            *reinterpret_cast<float4*>(&sm[T2 + d]) = v;
            if (t < 406) {
                stage_one(n, half, 0, t + 512, &sm[A2], &sm[C2], v, d);
                *reinterpret_cast<float4*>(&sm[T2 + d]) = v;
            }
        }
        __syncthreads();

        float acc0 = 0.f, acc1 = 0.f, acc2 = 0.f;

#pragma unroll 1
        for (int ck = 0; ck < 4; ck++) {
            // prefetch next chunk into regs (latency hidden by compute)
            float4 vA, vB; int dA = 0, dB = 0;
            if (ck < 3) {
                stage_one(n, half, ck + 1, t, &sm[A2], &sm[C2], vA, dA);
                if (t < 406) stage_one(n, half, ck + 1, t + 512, &sm[A2], &sm[C2], vB, dB);
            }

            const float* T = &sm[T2 + (ck & 1) * 4080];
#pragma unroll 2
            for (int cil = 0; cil < 6; cil++) {
                const int ci = ck * 6 + cil;
#pragma unroll
                for (int kh = 0; kh < 3; kh++) {
                    const int rl = 2 * r + kh;
                    const float* te = &T[cil * 680 + rl * 20];
                    float v0 = te[340 + wo];      // col 2wo-1
                    float v1 = te[wo];            // col 2wo
                    float v2 = te[341 + wo];      // col 2wo+1
                    const float* wb = &sm[W2 + ((ci * 3 + kh) * 4 + grp) * 12];
                    float4 wa = *reinterpret_cast<const float4*>(wb);
                    float4 wc = *reinterpret_cast<const float4*>(wb + 4);
                    float w8 = wb[8];
                    acc0 += v0 * wa.x + v1 * wa.y + v2 * wa.z;
                    acc1 += v0 * wa.w + v1 * wc.x + v2 * wc.y;
                    acc2 += v0 * wc.z + v1 * wc.w + v2 * w8;
                }
            }

            if (ck < 3) {
                float* Tn = &sm[T2 + ((ck + 1) & 1) * 4080];
                *reinterpret_cast<float4*>(&Tn[dA]) = vA;
                if (t < 406) *reinterpret_cast<float4*>(&Tn[dB]) = vB;
            }
            __syncthreads();
        }

        const int ho = half * 8 + r;
        const int cb = cg * 12 + grp * 3;
        g_y2[((n * 24 + cb + 0) * 16 + ho) * 16 + wo] = acc0;
        g_y2[((n * 24 + cb + 1) * 16 + ho) * 16 + wo] = acc1;
        g_y2[((n * 24 + cb + 2) * 16 + ho) * 16 + wo] = acc2;

        float av[3] = {acc0, acc1, acc2};
#pragma unroll
        for (int c3 = 0; c3 < 3; c3++) {
            float rs = warp_sum(av[c3]);
            float rq = warp_sum(av[c3] * av[c3]);
            if (lane == 0) {
                int ch = grp * 3 + c3;
                sm[RD2 + ch * 8 + w4 * 2] = rs;
                sm[RD2 + ch * 8 + w4 * 2 + 1] = rq;
            }
        }
        __syncthreads();
        if (t < 12) {
            float s = 0.f, q = 0.f;
#pragma unroll
            for (int w = 0; w < 4; w++) { s += sm[RD2 + t * 8 + w * 2]; q += sm[RD2 + t * 8 + w * 2 + 1]; }
            g_p2s[(cg * 12 + t) * 64 + n * 2 + half] = s;
            g_p2q[(cg * 12 + t) * 64 + n * 2 + half] = q;
        }
    }

    grid_barrier();

    // ============================ PHASE 3: head ============================
    // 128 blocks = 32n x 4 chunks (256 fc1 outputs each).
    {
        const int n = bid >> 2;
        const int chunk = bid & 3;

        compute_bn24(g_p2s, g_p2q, 1.f / 8192.f, bn2_g, bn2_b, &sm[HA], &sm[HC], t);
        if (t >= 384) sm[HQ + t - 384] = ques[n * 128 + t - 384];
        __syncthreads();

        // spatial sums of relu(bn2(y2)); coord sums are exactly 0
        if (t < 384) {
            int c = t >> 4, g = t & 15;
            const float* yp = &g_y2[(n * 24 + c) * 256 + g * 16];
            float a = sm[HA + c], cc = sm[HC + c];
            float acc = 0.f;
#pragma unroll
            for (int i = 0; i < 16; i++) acc += fmaxf(fmaf(a, yp[i], cc), 0.f);
            sm[HP + c * 16 + g] = acc;
        }
        __syncthreads();
        if (t < 26) {
            float s = 0.f;
            if (t < 24) {
#pragma unroll
                for (int g = 0; g < 16; g++) s += sm[HP + t * 16 + g];
            }
            sm[HS + t] = s;
        }
        __syncthreads();

        // relations: j = t&127, k-quarter kk = t>>7
        {
            const int j = t & 127, kk = t >> 7;
            float r2 = (kk == 0) ? b_rel[j] : 0.f;
            const float* wq = &w_rel[(52 + kk * 32) * 128 + j];
#pragma unroll 8
            for (int q = 0; q < 32; q++)
                r2 = fmaf(sm[HQ + kk * 32 + q], wq[q * 128], r2);
            sm[HRB + kk * 128 + j] = r2;
            if (kk == 0) {
                float r1 = 0.f;
#pragma unroll
                for (int k = 0; k < 26; k++)
                    r1 += sm[HS + k] * (w_rel[k * 128 + j] + w_rel[(26 + k) * 128 + j]);
                sm[HRA + j] = r1;
            }
        }
        __syncthreads();
        if (t < 128)
            sm[HR + t] = 256.f * sm[HRA + t] +
                         65536.f * (sm[HRB + t] + sm[HRB + 128 + t] +
                                    sm[HRB + 256 + t] + sm[HRB + 384 + t]);
        __syncthreads();

        // fc1: 256 outputs, k split in halves (kh2 = t>>8)
        {
            const int jj = t & 255, kh2 = t >> 8;
            const int j = chunk * 256 + jj;
            float acc = (kh2 == 0) ? b_fc1[j] : 0.f;
            const float* wp = &w_fc1[(kh2 * 64) * 1024 + j];
            const float* rp = &sm[HR + kh2 * 64];
#pragma unroll 16
            for (int k = 0; k < 64; k++)
                acc = fmaf(rp[k], wp[k * 1024], acc);
            sm[HH + t] = acc;
        }
        __syncthreads();
        // relu + partial fc2
        {
            float p0 = 0.f, p1 = 0.f;
            if (t < 256) {
                float hv = fmaxf(sm[HH + t] + sm[HH + t + 256], 0.f);
                const int j = chunk * 256 + t;
                p0 = hv * w_fc2[j * 2];
                p1 = hv * w_fc2[j * 2 + 1];
            }
            p0 = warp_sum(p0);
            p1 = warp_sum(p1);
            if (lane == 0 && warp < 8) { sm[HO + warp * 2] = p0; sm[HO + warp * 2 + 1] = p1; }
        }
        __syncthreads();
        if (t == 0) {
            float o0 = 0.f, o1 = 0.f;
#pragma unroll
            for (int w = 0; w < 8; w++) { o0 += sm[HO + w * 2]; o1 += sm[HO + w * 2 + 1]; }
            g_hpart[(n * 4 + chunk) * 2 + 0] = o0;
            g_hpart[(n * 4 + chunk) * 2 + 1] = o1;
            __threadfence();
            unsigned r = atomicAdd(&g_done[n], 1u);
            if (r == 3) {
                __threadfence();
                float f0 = b_fc2[0], f1 = b_fc2[1];
#pragma unroll
                for (int c = 0; c < 4; c++) {
                    f0 += g_hpart[(n * 4 + c) * 2 + 0];
                    f1 += g_hpart[(n * 4 + c) * 2 + 1];
                }
                out[n * 2 + 0] = f0;
                out[n * 2 + 1] = f1;
                g_done[n] = 0;
            }
        }
    }
}

// ---------------- launch ----------------
extern "C" void kernel_launch(void* const* d_in, const int* in_sizes, int n_in,
                              void* d_out, int out_size) {
    (void)in_sizes; (void)n_in; (void)out_size;
    const float* image   = (const float*)d_in[0];
    const float* ques    = (const float*)d_in[1];
    const float* conv1_w = (const float*)d_in[2];
    const float* bn1_g   = (const float*)d_in[4];
    const float* bn1_b   = (const float*)d_in[5];
    const float* conv2_w = (const float*)d_in[6];
    const float* bn2_g   = (const float*)d_in[8];
    const float* bn2_b   = (const float*)d_in[9];
    const float* w_rel   = (const float*)d_in[10];
    const float* b_rel   = (const float*)d_in[11];
    const float* w_fc1   = (const float*)d_in[12];
    const float* b_fc1   = (const float*)d_in[13];
    const float* w_fc2   = (const float*)d_in[14];
    const float* b_fc2   = (const float*)d_in[15];
    float* out = (float*)d_out;

    fused_kernel<<<NB, 512>>>(image, conv1_w, bn1_g, bn1_b,
                              conv2_w, bn2_g, bn2_b,
                              ques, w_rel, b_rel,
                              w_fc1, b_fc1, w_fc2, b_fc2, out);
}

// round 12
// speedup vs baseline: 1.5302x; 1.0716x over previous
#include <cuda_runtime.h>

// ---------------- scratch ----------------
// y1 de-interleaved: [n][ci24][33 rows][36]; stored row = y1row+1;
// off j in [0,16): col 2j ("ev"); off 16+j, j in [0,17): col 2j-1 ("od", j=0 pad)
__device__ float g_y1[32 * 24 * 33 * 36];
__device__ float g_y2[32 * 24 * 16 * 16];
__device__ float g_p1s[24 * 64];          // key n*2+h16
__device__ float g_p1q[24 * 64];
__device__ float g_p2s[24 * 64];          // key n*2+half
__device__ float g_p2q[24 * 64];
__device__ float g_hpart[32 * 4 * 2];
__device__ unsigned g_done[32];           // zero-init, self-reset

__device__ __forceinline__ float warp_sum(float v) {
#pragma unroll
    for (int o = 16; o > 0; o >>= 1) v += __shfl_down_sync(0xffffffffu, v, o);
    return v;
}

__device__ __forceinline__ void compute_bn24(const float* __restrict__ ps,
                                             const float* __restrict__ pq,
                                             float invM,
                                             const float* __restrict__ gamma,
                                             const float* __restrict__ beta,
                                             float* s_a, float* s_c, int t) {
    if (t < 192) {
        int c = t >> 3, g = t & 7;
        float s = 0.f, q = 0.f;
        for (int i = g; i < 64; i += 8) { s += ps[c * 64 + i]; q += pq[c * 64 + i]; }
#pragma unroll
        for (int o = 4; o > 0; o >>= 1) {
            s += __shfl_down_sync(0xffffffffu, s, o, 8);
            q += __shfl_down_sync(0xffffffffu, q, o, 8);
        }
        if (g == 0) {
            float mean = s * invM;
            float var  = q * invM - mean * mean;
            float a    = gamma[c] * rsqrtf(var + 1e-5f);
            s_a[c] = a;
            s_c[c] = beta[c] - mean * a;
        }
    }
}

// ============================== conv1 kernel ==============================
// 128 blocks = 32n x 2 h16 x 2 cg(12co). 512 thr = 16 out rows x 32 cols.
#define EV1 0            // [3][33][32]  3168
#define OD1 3168         // [3][33][33]  3267 (col0 pad)
#define W1  6448         // [(ci*3+kh)*3+kw][12] 324
#define RD1 6784         // [12][16][2]  384

__global__ void __launch_bounds__(512, 1) conv1_kernel(
    const float* __restrict__ image, const float* __restrict__ w1) {
    __shared__ __align__(16) float sm[7168];
    const int bid = blockIdx.x, t = threadIdx.x;
    const int warp = t >> 5, lane = t & 31;
    const int n = bid >> 2, h16 = (bid >> 1) & 1, cg = bid & 1;

#pragma unroll
    for (int i = 0; i < 4; i++) {
        int idx = t + i * 512;
        if (idx < 1584) {
            int ci  = idx / 528;
            int rem = idx - ci * 528;
            int row = rem >> 4, c4 = rem & 15;
            int hg  = 32 * h16 - 1 + row;
            float4 v = make_float4(0.f, 0.f, 0.f, 0.f);
            if (hg >= 0)
                v = *reinterpret_cast<const float4*>(
                    &image[((n * 3 + ci) * 64 + hg) * 64 + c4 * 4]);
            *reinterpret_cast<float2*>(&sm[EV1 + ci * 1056 + row * 32 + 2 * c4]) =
                make_float2(v.x, v.z);
            sm[OD1 + ci * 1089 + row * 33 + 2 * c4 + 1] = v.y;
            sm[OD1 + ci * 1089 + row * 33 + 2 * c4 + 2] = v.w;
        }
    }
    if (t < 99) sm[OD1 + (t / 33) * 1089 + (t % 33) * 33] = 0.f;
    if (t < 324) {
        int co = t / 27, rem = t % 27;
        int ci = rem / 9, kh = (rem % 9) / 3, kw = rem % 3;
        sm[W1 + ((ci * 3 + kh) * 3 + kw) * 12 + co] = w1[(cg * 12 + co) * 27 + rem];
    }
    __syncthreads();

    const int r = t >> 5, wo = t & 31;
    float acc[12];
#pragma unroll
    for (int co = 0; co < 12; co++) acc[co] = 0.f;

#pragma unroll 1
    for (int ci = 0; ci < 3; ci++) {
#pragma unroll
        for (int kh = 0; kh < 3; kh++) {
            const int rl = 2 * r + kh;
            float vv[3];
            vv[0] = sm[OD1 + ci * 1089 + rl * 33 + wo];
            vv[1] = sm[EV1 + ci * 1056 + rl * 32 + wo];
            vv[2] = sm[OD1 + ci * 1089 + rl * 33 + wo + 1];
            const float4* wp = reinterpret_cast<const float4*>(&sm[W1 + (ci * 3 + kh) * 36]);
#pragma unroll
            for (int kw = 0; kw < 3; kw++) {
                float v = vv[kw];
                float4 a = wp[kw * 3], b = wp[kw * 3 + 1], c = wp[kw * 3 + 2];
                acc[0] += v * a.x;  acc[1] += v * a.y;  acc[2]  += v * a.z;  acc[3]  += v * a.w;
                acc[4] += v * b.x;  acc[5] += v * b.y;  acc[6]  += v * b.z;  acc[7]  += v * b.w;
                acc[8] += v * c.x;  acc[9] += v * c.y;  acc[10] += v * c.z;  acc[11] += v * c.w;
            }
        }
    }

    {
        const int off = (wo & 1) ? (17 + (wo >> 1)) : (wo >> 1);
        const int row_s = 16 * h16 + r + 1;
#pragma unroll
        for (int co = 0; co < 12; co++)
            g_y1[((n * 24 + cg * 12 + co) * 33 + row_s) * 36 + off] = acc[co];
    }

#pragma unroll
    for (int co = 0; co < 12; co++) {
        float rs = warp_sum(acc[co]);
        float rq = warp_sum(acc[co] * acc[co]);
        if (lane == 0) { sm[RD1 + co * 32 + warp * 2] = rs; sm[RD1 + co * 32 + warp * 2 + 1] = rq; }
    }
    __syncthreads();
    if (t < 12) {
        float s = 0.f, q = 0.f;
#pragma unroll
        for (int w = 0; w < 16; w++) { s += sm[RD1 + t * 32 + w * 2]; q += sm[RD1 + t * 32 + w * 2 + 1]; }
        g_p1s[(cg * 12 + t) * 64 + n * 2 + h16] = s;
        g_p1q[(cg * 12 + t) * 64 + n * 2 + h16] = q;
    }
}

// ============================== conv2 kernel ==============================
// 128 blocks = 32n x 2 half x 2 cg. Quad input layout: per ci a [17][16] array
// of float4 quads (v0,v1,v2,_), v's = cols (2j-1, 2j, 2j+1).
#define TQ  0            // 6 ci x 1088 = 6528
#define W2  6528         // [((ci*3+kh)*4+grp)][12] 3456
#define A2  9984
#define C2  10008
#define RD2 10032        // [12][4][2] 96

struct StageV { float fe[4]; float fo[5]; int dst; };

__device__ __forceinline__ void stage_quad_load(int n, int half, int ck, int idx,
                                                const float* sA, const float* sC,
                                                StageV& sv) {
    int ci_l = idx >> 6 ? idx / 68 : idx / 68;   // idx/68
    ci_l = idx / 68;
    int rem = idx - ci_l * 68;
    int row = rem >> 2, jg = (rem & 3) << 2;
    int ci  = ck * 6 + ci_l;
    const float* rowp = &g_y1[((n * 24 + ci) * 33 + 16 * half + row) * 36];
    float4 ev  = *reinterpret_cast<const float4*>(rowp + jg);
    float4 od4 = *reinterpret_cast<const float4*>(rowp + 16 + jg);
    float  od5 = rowp[20 + jg];
    float a = sA[ci], c = sC[ci];
    sv.fe[0] = fmaxf(fmaf(a, ev.x, c), 0.f);
    sv.fe[1] = fmaxf(fmaf(a, ev.y, c), 0.f);
    sv.fe[2] = fmaxf(fmaf(a, ev.z, c), 0.f);
    sv.fe[3] = fmaxf(fmaf(a, ev.w, c), 0.f);
    sv.fo[0] = fmaxf(fmaf(a, od4.x, c), 0.f);
    sv.fo[1] = fmaxf(fmaf(a, od4.y, c), 0.f);
    sv.fo[2] = fmaxf(fmaf(a, od4.z, c), 0.f);
    sv.fo[3] = fmaxf(fmaf(a, od4.w, c), 0.f);
    sv.fo[4] = fmaxf(fmaf(a, od5, c), 0.f);
    if (jg == 0) sv.fo[0] = 0.f;                       // col -1 pad
    if (half + row == 0) {                             // y1 row -1 pad
#pragma unroll
        for (int i = 0; i < 4; i++) sv.fe[i] = 0.f;
#pragma unroll
        for (int i = 0; i < 5; i++) sv.fo[i] = 0.f;
    }
    sv.dst = ci_l * 1088 + row * 64 + jg * 4;
}

__device__ __forceinline__ void stage_quad_store(float* smem, const StageV& sv) {
#pragma unroll
    for (int k = 0; k < 4; k++)
        *reinterpret_cast<float4*>(&smem[TQ + sv.dst + k * 4]) =
            make_float4(sv.fo[k], sv.fe[k], sv.fo[k + 1], 0.f);
}

__global__ void __launch_bounds__(512, 1) conv2_kernel(
    const float* __restrict__ w2,
    const float* __restrict__ bn1_g, const float* __restrict__ bn1_b) {
    __shared__ __align__(16) float sm[10128];
    const int bid = blockIdx.x, t = threadIdx.x;
    const int warp = t >> 5, lane = t & 31;
    const int n = bid >> 2, half = (bid >> 1) & 1, cg = bid & 1;

    compute_bn24(g_p1s, g_p1q, 1.f / 32768.f, bn1_g, bn1_b, &sm[A2], &sm[C2], t);

    for (int idx = t; idx < 2592; idx += 512) {
        int co = idx / 216, rem = idx % 216;
        int ci = rem / 9, kh = (rem % 9) / 3, kw = rem % 3;
        sm[W2 + ((ci * 3 + kh) * 4 + co / 3) * 12 + (co % 3) * 3 + kw] =
            w2[((cg * 12 + co) * 24 + ci) * 9 + kh * 3 + kw];
    }
    __syncthreads();   // BN consts ready

    const int w4 = warp & 3;
    const int grp = t >> 7;
    const int wo = (lane & 7) | ((w4 & 1) << 3);
    const int r  = (lane >> 3) | ((w4 >> 1) << 2);

    // stage chunk 0
    if (t < 408) {
        StageV sv;
        stage_quad_load(n, half, 0, t, &sm[A2], &sm[C2], sv);
        stage_quad_store(sm, sv);
    }
    __syncthreads();

    float acc0 = 0.f, acc1 = 0.f, acc2 = 0.f;

#pragma unroll 1
    for (int ck = 0; ck < 4; ck++) {
        StageV sv;
        const bool pf = (ck < 3) && (t < 408);
        if (pf) stage_quad_load(n, half, ck + 1, t, &sm[A2], &sm[C2], sv);

#pragma unroll 2
        for (int cil = 0; cil < 6; cil++) {
            const int ci = ck * 6 + cil;
#pragma unroll
            for (int kh = 0; kh < 3; kh++) {
                const int rl = 2 * r + kh;
                float4 q = *reinterpret_cast<const float4*>(
                    &sm[TQ + cil * 1088 + rl * 64 + wo * 4]);
                const float* wb = &sm[W2 + ((ci * 3 + kh) * 4 + grp) * 12];
                float4 wa = *reinterpret_cast<const float4*>(wb);
                float4 wc = *reinterpret_cast<const float4*>(wb + 4);
                float w8 = wb[8];
                acc0 += q.x * wa.x + q.y * wa.y + q.z * wa.z;
                acc1 += q.x * wa.w + q.y * wc.x + q.z * wc.y;
                acc2 += q.x * wc.z + q.y * wc.w + q.z * w8;
            }
        }
        __syncthreads();
        if (pf) stage_quad_store(sm, sv);
        __syncthreads();
    }

    const int ho = half * 8 + r;
    const int cb = cg * 12 + grp * 3;
    g_y2[((n * 24 + cb + 0) * 16 + ho) * 16 + wo] = acc0;
    g_y2[((n * 24 + cb + 1) * 16 + ho) * 16 + wo] = acc1;
    g_y2[((n * 24 + cb + 2) * 16 + ho) * 16 + wo] = acc2;

    float av[3] = {acc0, acc1, acc2};
#pragma unroll
    for (int c3 = 0; c3 < 3; c3++) {
        float rs = warp_sum(av[c3]);
        float rq = warp_sum(av[c3] * av[c3]);
        if (lane == 0) {
            int ch = grp * 3 + c3;
            sm[RD2 + ch * 8 + w4 * 2] = rs;
            sm[RD2 + ch * 8 + w4 * 2 + 1] = rq;
        }
    }
    __syncthreads();
    if (t < 12) {
        float s = 0.f, q = 0.f;
#pragma unroll
        for (int w = 0; w < 4; w++) { s += sm[RD2 + t * 8 + w * 2]; q += sm[RD2 + t * 8 + w * 2 + 1]; }
        g_p2s[(cg * 12 + t) * 64 + n * 2 + half] = s;
        g_p2q[(cg * 12 + t) * 64 + n * 2 + half] = q;
    }
}

// ============================== head kernel ==============================
#define HQ   0
#define HA   128
#define HC   152
#define HP   176         // 24*16
#define HS   560
#define HRA  592
#define HRB  720
#define HR   1232
#define HH   1360
#define HO   1872

__global__ void __launch_bounds__(512, 1) head_kernel(
    const float* __restrict__ ques,
    const float* __restrict__ bn2_g, const float* __restrict__ bn2_b,
    const float* __restrict__ w_rel, const float* __restrict__ b_rel,
    const float* __restrict__ w_fc1, const float* __restrict__ b_fc1,
    const float* __restrict__ w_fc2, const float* __restrict__ b_fc2,
    float* __restrict__ out) {
    __shared__ __align__(16) float sm[1888];
    const int bid = blockIdx.x, t = threadIdx.x;
    const int warp = t >> 5, lane = t & 31;
    const int n = bid >> 2, chunk = bid & 3;

    compute_bn24(g_p2s, g_p2q, 1.f / 8192.f, bn2_g, bn2_b, &sm[HA], &sm[HC], t);
    if (t >= 384) sm[HQ + t - 384] = ques[n * 128 + t - 384];
    __syncthreads();

    if (t < 384) {
        int c = t >> 4, g = t & 15;
        const float* yp = &g_y2[(n * 24 + c) * 256 + g * 16];
        float a = sm[HA + c], cc = sm[HC + c];
        float acc = 0.f;
#pragma unroll
        for (int i = 0; i < 16; i++) acc += fmaxf(fmaf(a, yp[i], cc), 0.f);
        sm[HP + c * 16 + g] = acc;
    }
    __syncthreads();
    if (t < 26) {
        float s = 0.f;
        if (t < 24) {
#pragma unroll
            for (int g = 0; g < 16; g++) s += sm[HP + t * 16 + g];
        }
        sm[HS + t] = s;
    }
    __syncthreads();

    {
        const int j = t & 127, kk = t >> 7;
        float r2 = (kk == 0) ? b_rel[j] : 0.f;
        const float* wq = &w_rel[(52 + kk * 32) * 128 + j];
#pragma unroll 8
        for (int q = 0; q < 32; q++)
            r2 = fmaf(sm[HQ + kk * 32 + q], wq[q * 128], r2);
        sm[HRB + kk * 128 + j] = r2;
        if (kk == 0) {
            float r1 = 0.f;
#pragma unroll
            for (int k = 0; k < 26; k++)
                r1 += sm[HS + k] * (w_rel[k * 128 + j] + w_rel[(26 + k) * 128 + j]);
            sm[HRA + j] = r1;
        }
    }
    __syncthreads();
    if (t < 128)
        sm[HR + t] = 256.f * sm[HRA + t] +
                     65536.f * (sm[HRB + t] + sm[HRB + 128 + t] +
                                sm[HRB + 256 + t] + sm[HRB + 384 + t]);
    __syncthreads();

    {
        const int jj = t & 255, kh2 = t >> 8;
        const int j = chunk * 256 + jj;
        float acc = (kh2 == 0) ? b_fc1[j] : 0.f;
        const float* wp = &w_fc1[(kh2 * 64) * 1024 + j];
        const float* rp = &sm[HR + kh2 * 64];
#pragma unroll 16
        for (int k = 0; k < 64; k++)
            acc = fmaf(rp[k], wp[k * 1024], acc);
        sm[HH + t] = acc;
    }
    __syncthreads();
    {
        float p0 = 0.f, p1 = 0.f;
        if (t < 256) {
            float hv = fmaxf(sm[HH + t] + sm[HH + t + 256], 0.f);
            const int j = chunk * 256 + t;
            p0 = hv * w_fc2[j * 2];
            p1 = hv * w_fc2[j * 2 + 1];
        }
        p0 = warp_sum(p0);
        p1 = warp_sum(p1);
        if (lane == 0 && warp < 8) { sm[HO + warp * 2] = p0; sm[HO + warp * 2 + 1] = p1; }
    }
    __syncthreads();
    if (t == 0) {
        float o0 = 0.f, o1 = 0.f;
#pragma unroll
        for (int w = 0; w < 8; w++) { o0 += sm[HO + w * 2]; o1 += sm[HO + w * 2 + 1]; }
        g_hpart[(n * 4 + chunk) * 2 + 0] = o0;
        g_hpart[(n * 4 + chunk) * 2 + 1] = o1;
        __threadfence();
        unsigned r = atomicAdd(&g_done[n], 1u);
        if (r == 3) {
            __threadfence();
            float f0 = b_fc2[0], f1 = b_fc2[1];
#pragma unroll
            for (int c = 0; c < 4; c++) {
                f0 += g_hpart[(n * 4 + c) * 2 + 0];
                f1 += g_hpart[(n * 4 + c) * 2 + 1];
            }
            out[n * 2 + 0] = f0;
            out[n * 2 + 1] = f1;
            g_done[n] = 0;
        }
    }
}

// ---------------- launch ----------------
extern "C" void kernel_launch(void* const* d_in, const int* in_sizes, int n_in,
                              void* d_out, int out_size) {
    (void)in_sizes; (void)n_in; (void)out_size;
    const float* image   = (const float*)d_in[0];
    const float* ques    = (const float*)d_in[1];
    const float* conv1_w = (const float*)d_in[2];
    const float* bn1_g   = (const float*)d_in[4];
    const float* bn1_b   = (const float*)d_in[5];
    const float* conv2_w = (const float*)d_in[6];
    const float* bn2_g   = (const float*)d_in[8];
    const float* bn2_b   = (const float*)d_in[9];
    const float* w_rel   = (const float*)d_in[10];
    const float* b_rel   = (const float*)d_in[11];
    const float* w_fc1   = (const float*)d_in[12];
    const float* b_fc1   = (const float*)d_in[13];
    const float* w_fc2   = (const float*)d_in[14];
    const float* b_fc2   = (const float*)d_in[15];
    float* out = (float*)d_out;

    conv1_kernel<<<128, 512>>>(image, conv1_w);
    conv2_kernel<<<128, 512>>>(conv2_w, bn1_g, bn1_b);
    head_kernel<<<128, 512>>>(ques, bn2_g, bn2_b, w_rel, b_rel,
                              w_fc1, b_fc1, w_fc2, b_fc2, out);
}